// round 12
// baseline (speedup 1.0000x reference)
#include <cuda_runtime.h>
#include <cuda_bf16.h>
#include <math.h>
#include <stdint.h>

#define BATCH 16
#define NPTS 2048
#define NG 128
#define GS 32
#define O1 64
#define O2 96
#define FEATD 1024
#define NBRK 38
#define SUP 8
#define NBH 32

// ----------------------------- scratch (static device globals) ---------------
__device__ int   g_fps[BATCH*NG];
__device__ float g_center[BATCH*NG*3];
__device__ int   g_knnc[BATCH*NG*GS];
__device__ __align__(16) float g_reb0[BATCH*2048*3];
__device__ __align__(16) float g_reb1[BATCH*1024*3];
__device__ __align__(16) float g_encin2[BATCH*1024*3];
__device__ __align__(16) float g_gmax[BATCH*256];
__device__ __align__(16) float g_gb[BATCH*512];
__device__ float g_cmpart[256*1024];
__device__ __align__(16) float g_feat[BATCH*1024];
__device__ __align__(16) float g_feat2[BATCH*1024];
__device__ __align__(16) float g_dec1[BATCH*2048];
__device__ __align__(16) float g_dec2[BATCH*2048];
__device__ __align__(16) float g_dec3[BATCH*2048];
__device__ __align__(16) float g_pred[BATCH*2048*3];
__device__ int   g_knngA[BATCH*64*38];
__device__ int   g_knngB[BATCH*32*38];
__device__ int   g_knngC[BATCH*32*32];
__device__ __align__(16) float g_gathA[BATCH*2432*3];
__device__ __align__(16) float g_gathB[BATCH*1216*3];
__device__ int   g_knnp[BATCH*2048*32];
__device__ float g_normals[BATCH*2048*3];
__device__ float g_std[BATCH*2048];
__device__ float g_partA1[128];
__device__ float g_partA2[160];
__device__ float g_partB1[64];
__device__ float g_partB2[80];
__device__ float g_loss[4];

// split (bf16 hi/lo packed pairs) buffers
__device__ __align__(16) uint32_t g_w2h[256*64],    g_w2l[256*64];
__device__ __align__(16) uint32_t g_w3h[512*128],   g_w3l[512*128];
__device__ __align__(16) uint32_t g_w4h[1024*256],  g_w4l[1024*256];
__device__ __align__(16) uint32_t g_h1h[BATCH*2048*64],  g_h1l[BATCH*2048*64];
__device__ __align__(16) uint32_t g_h2h[BATCH*2048*128], g_h2l[BATCH*2048*128];
__device__ __align__(16) uint32_t g_h4h[BATCH*2048*256], g_h4l[BATCH*2048*256];

// ----------------------------- helpers ---------------------------------------
__device__ __forceinline__ uint32_t packsplit(float a, float b, uint32_t& lo) {
    __nv_bfloat16 ha = __float2bfloat16_rn(a);
    __nv_bfloat16 hb = __float2bfloat16_rn(b);
    __nv_bfloat16 la = __float2bfloat16_rn(a - __bfloat162float(ha));
    __nv_bfloat16 lb = __float2bfloat16_rn(b - __bfloat162float(hb));
    __nv_bfloat162 l2 = __halves2bfloat162(la, lb);
    __nv_bfloat162 h2 = __halves2bfloat162(ha, hb);
    lo = *(uint32_t*)&l2;
    return *(uint32_t*)&h2;
}
__device__ __forceinline__ void mma_bf16(float* d, const uint32_t* a, const uint32_t* b) {
    asm volatile("mma.sync.aligned.m16n8k16.row.col.f32.bf16.bf16.f32 "
        "{%0,%1,%2,%3}, {%4,%5,%6,%7}, {%8,%9}, {%0,%1,%2,%3};"
        : "+f"(d[0]), "+f"(d[1]), "+f"(d[2]), "+f"(d[3])
        : "r"(a[0]), "r"(a[1]), "r"(a[2]), "r"(a[3]), "r"(b[0]), "r"(b[1]));
}
__device__ __forceinline__ void atomMaxF(float* a, float v) {
    if (v >= 0.f) atomicMax((int*)a, __float_as_int(v));
    else atomicMin((unsigned int*)a, __float_as_uint(v));
}
__device__ __forceinline__ uint32_t s2a(const void* p) {
    return (uint32_t)__cvta_generic_to_shared(p);
}
__device__ __forceinline__ void cpasync16(uint32_t saddr, const void* g) {
    asm volatile("cp.async.cg.shared.global [%0], [%1], 16;" :: "r"(saddr), "l"(g));
}

// ----------------------------- FPS (512 thr, 1 barrier/round) -----------------
__global__ void fps_kernel(const float* __restrict__ pts, int* __restrict__ out) {
    __shared__ float sx[NPTS], sy[NPTS], sz[NPTS];
    __shared__ unsigned long long slot[NG];
    int b = blockIdx.x, t = threadIdx.x, lane = t & 31;
    const float* p = pts + (size_t)b*NPTS*3;
    for (int i = t; i < NPTS; i += 512) {
        sx[i] = p[3*i]; sy[i] = p[3*i+1]; sz[i] = p[3*i+2];
    }
    for (int i = t; i < NG; i += 512) slot[i] = 0ULL;
    float px[4], py[4], pz[4], dv[4];
    #pragma unroll
    for (int r = 0; r < 4; r++) {
        int i = t + r*512;
        px[r] = p[3*i]; py[r] = p[3*i+1]; pz[r] = p[3*i+2];
        dv[r] = 1e10f;
    }
    __syncthreads();
    int far = 0;
    for (int g = 0; g < NG; g++) {
        if (t == 0) out[b*NG + g] = far;
        float cx = sx[far], cy = sy[far], cz = sz[far];
        float bv = 0.f; int bi = 0;
        #pragma unroll
        for (int r = 0; r < 4; r++) {
            float dx = px[r]-cx, dy = py[r]-cy, dz = pz[r]-cz;
            float d = dx*dx + dy*dy + dz*dz;
            float m = fminf(dv[r], d);
            dv[r] = m;
            if (r == 0) { bv = m; bi = t; }
            else if (m > bv) { bv = m; bi = t + r*512; }
        }
        #pragma unroll
        for (int off = 16; off > 0; off >>= 1) {
            float ov = __shfl_down_sync(0xffffffffu, bv, off);
            int   oi = __shfl_down_sync(0xffffffffu, bi, off);
            if (ov > bv || (ov == bv && oi < bi)) { bv = ov; bi = oi; }
        }
        if (lane == 0) {
            unsigned long long key =
                ((unsigned long long)__float_as_uint(bv) << 32) |
                (unsigned long long)(unsigned)(~bi);
            atomicMax(&slot[g], key);
        }
        __syncthreads();
        far = (int)(~(unsigned)(slot[g] & 0xffffffffu));
    }
}

// ----------------------------- gather ----------------------------------------
__global__ void gather3_kernel(const float* __restrict__ db, int dbstride,
                               const int* __restrict__ idx, int idxstride,
                               int cnt, float* __restrict__ out) {
    int gid = blockIdx.x*blockDim.x + threadIdx.x;
    if (gid >= BATCH*cnt) return;
    int b = gid / cnt, i = gid % cnt;
    int j = idx[b*idxstride + i];
    const float* s = db + ((size_t)b*dbstride + j)*3;
    float* o = out + (size_t)gid*3;
    o[0] = s[0]; o[1] = s[1]; o[2] = s[2];
}

// ----------------------------- kNN (per-warp top-k + 8-way merge) -------------
// db size fixed at 2048, 256 threads, 8 dists/thread in registers.
// Phase 1: each warp selects its own sorted top-k over its 256 points using
// warp-internal shuffle reduces (ZERO block barriers). Phase 2: one barrier,
// then warp 0 merges the 8 sorted lists. Comparator (dist, idx) lex-min
// everywhere -> output identical to global iterative-min selection.
__global__ void knn_kernel(const float* __restrict__ q, int qstride, int nq,
                           const float* __restrict__ db, int dbstride,
                           int k, int* __restrict__ out) {
    __shared__ float lv[8][40];
    __shared__ int   li[8][40];
    int b = blockIdx.x / nq, qi = blockIdx.x % nq;
    int t = threadIdx.x, lane = t & 31, wid = t >> 5;
    const float* qp = q + ((size_t)b*qstride + qi)*3;
    float qx = qp[0], qy = qp[1], qz = qp[2];
    const float* dp = db + (size_t)b*dbstride*3;
    float dv[8];
    #pragma unroll
    for (int r = 0; r < 8; r++) {
        int i = t + r*256;
        float dx = dp[3*i]-qx, dy = dp[3*i+1]-qy, dz = dp[3*i+2]-qz;
        dv[r] = dx*dx + dy*dy + dz*dz;
    }
    float lmv = 3.9e38f; int lmi = (1<<30);
    #pragma unroll
    for (int r = 0; r < 8; r++)
        if (dv[r] < lmv) { lmv = dv[r]; lmi = t + r*256; }

    // phase 1: per-warp sorted top-k (no block barriers)
    for (int s = 0; s < k; s++) {
        float rv = lmv; int ri = lmi;
        #pragma unroll
        for (int off = 16; off > 0; off >>= 1) {
            float ov = __shfl_down_sync(0xffffffffu, rv, off);
            int   oi = __shfl_down_sync(0xffffffffu, ri, off);
            if (ov < rv || (ov == rv && oi < ri)) { rv = ov; ri = oi; }
        }
        rv = __shfl_sync(0xffffffffu, rv, 0);
        ri = __shfl_sync(0xffffffffu, ri, 0);
        if (lane == 0) { lv[wid][s] = rv; li[wid][s] = ri; }
        if (lane == ((ri & 255) & 31)) {      // owner lane updates its cache
            int r0 = ri >> 8;
            #pragma unroll
            for (int r = 0; r < 8; r++) if (r == r0) dv[r] = 3.9e38f;
            lmv = 3.9e38f; lmi = (1<<30);
            #pragma unroll
            for (int r = 0; r < 8; r++)
                if (dv[r] < lmv) { lmv = dv[r]; lmi = t + r*256; }
        }
    }
    __syncthreads();

    // phase 2: warp 0 merges 8 sorted lists (lane j tracks list j's head)
    if (wid == 0) {
        int ptr = 0;
        int* op = out + ((size_t)b*nq + qi)*k;
        for (int s = 0; s < k; s++) {
            float rv = (lane < 8) ? lv[lane][ptr] : 3.9e38f;
            int   ri = (lane < 8) ? li[lane][ptr] : (1<<30);
            int   rl = lane;
            #pragma unroll
            for (int off = 4; off > 0; off >>= 1) {
                float ov = __shfl_down_sync(0xffffffffu, rv, off);
                int   oi = __shfl_down_sync(0xffffffffu, ri, off);
                int   ol = __shfl_down_sync(0xffffffffu, rl, off);
                if (ov < rv || (ov == rv && oi < ri)) { rv = ov; ri = oi; rl = ol; }
            }
            ri = __shfl_sync(0xffffffffu, ri, 0);
            rl = __shfl_sync(0xffffffffu, rl, 0);
            if (lane == 0) op[s] = ri;
            if (lane == rl) ptr++;
        }
    }
}

// ----------------------------- weight splitting -------------------------------
__global__ void splitw_kernel(const float* __restrict__ W, int ld, int coloff,
                              int total, int cols2,
                              uint32_t* __restrict__ Oh, uint32_t* __restrict__ Ol) {
    int gid = blockIdx.x*256 + threadIdx.x;
    if (gid >= total) return;
    int n = gid / cols2, j = gid % cols2;
    float a = W[(size_t)n*ld + coloff + 2*j];
    float b = W[(size_t)n*ld + coloff + 2*j + 1];
    uint32_t lo;
    uint32_t hi = packsplit(a, b, lo);
    Oh[gid] = hi; Ol[gid] = lo;
}

// ----------------------------- encoder layer 1 (K=3), split output ------------
__global__ void layer1_kernel(const float* __restrict__ x,
                              const float* __restrict__ W1, const float* __restrict__ b1,
                              const float* __restrict__ g1, const float* __restrict__ be1,
                              const float* __restrict__ m1, const float* __restrict__ v1,
                              uint32_t* __restrict__ h1h, uint32_t* __restrict__ h1l,
                              int M) {
    int gid = blockIdx.x*256 + threadIdx.x;
    if (gid >= M*64) return;
    int m = gid >> 6, j = gid & 63;
    const float* xp = x + (size_t)m*3;
    float x0 = xp[0], x1 = xp[1], x2 = xp[2];
    float v[2];
    #pragma unroll
    for (int h = 0; h < 2; h++) {
        int n = 2*j + h;
        float acc = x0*W1[n*3] + x1*W1[n*3+1] + x2*W1[n*3+2] + b1[n];
        float sc = rsqrtf(v1[n] + 1e-5f);
        float val = (acc - m1[n]) * sc * g1[n] + be1[n];
        v[h] = fmaxf(val, 0.f);
    }
    uint32_t lo;
    uint32_t hi = packsplit(v[0], v[1], lo);
    h1h[gid] = hi; h1l[gid] = lo;
}

// ----------------------------- tensor-core GEMM (3x bf16 split, cp.async) -----
#define GSTG 15360         // u32 per stage
#define GOFF_AL 5120
#define GOFF_WH 10240
#define GOFF_WL 12800

__device__ __forceinline__ void gemm_issue(uint32_t* stg,
        const uint32_t* Ah, const uint32_t* Al, int lda2,
        const uint32_t* Wh, const uint32_t* Wl, int ldw2,
        int m0, int n0, int k2, int tid) {
    #pragma unroll
    for (int p = 0; p < 2; p++) {
        int idx = tid + p*512;
        int r = idx >> 2, sl = idx & 3;
        size_t go = (size_t)(m0 + r)*lda2 + k2 + sl*4;
        cpasync16(s2a(stg + r*20 + sl*4), Ah + go);
        cpasync16(s2a(stg + GOFF_AL + r*20 + sl*4), Al + go);
    }
    {
        int idx = tid;
        int r = idx >> 2, sl = idx & 3;
        size_t go = (size_t)(n0 + r)*ldw2 + k2 + sl*4;
        cpasync16(s2a(stg + GOFF_WH + r*20 + sl*4), Wh + go);
        cpasync16(s2a(stg + GOFF_WL + r*20 + sl*4), Wl + go);
    }
    asm volatile("cp.async.commit_group;" ::: "memory");
}

__global__ __launch_bounds__(512, 1) void gemm_tc(
        const uint32_t* __restrict__ Ah, const uint32_t* __restrict__ Al, int lda2,
        const uint32_t* __restrict__ Wh, const uint32_t* __restrict__ Wl, int ldw2,
        int M, int N, int K,
        const float* __restrict__ bias,
        const float* __restrict__ bbias, int npb,
        const float* __restrict__ bng, const float* __restrict__ bnb,
        const float* __restrict__ bnm, const float* __restrict__ bnv,
        int relu,
        uint32_t* __restrict__ Ch, uint32_t* __restrict__ Cl,
        float* __restrict__ maxpart) {
    extern __shared__ uint32_t dsm[];
    __shared__ float smax[128];
    int tid = threadIdx.x;
    int warp = tid >> 5, lane = tid & 31;
    int wm = (warp >> 2) * 64, wn = (warp & 3) * 32;
    int m0 = blockIdx.y * 256, n0 = blockIdx.x * 128;
    int g = lane >> 2, tg = lane & 3;

    if (maxpart && tid < 128) smax[tid] = -3.4e38f;

    float acc[4][4][4];
    #pragma unroll
    for (int mi = 0; mi < 4; mi++)
        #pragma unroll
        for (int ni = 0; ni < 4; ni++)
            #pragma unroll
            for (int r = 0; r < 4; r++) acc[mi][ni][r] = 0.f;

    int nch = K / 32;
    gemm_issue(dsm, Ah, Al, lda2, Wh, Wl, ldw2, m0, n0, 0, tid);
    if (nch > 1) gemm_issue(dsm + GSTG, Ah, Al, lda2, Wh, Wl, ldw2, m0, n0, 16, tid);

    for (int c = 0; c < nch; c++) {
        if (c < nch - 1) asm volatile("cp.async.wait_group 1;" ::: "memory");
        else             asm volatile("cp.async.wait_group 0;" ::: "memory");
        __syncthreads();
        if (c + 2 < nch)
            gemm_issue(dsm + ((c+2)%3)*GSTG, Ah, Al, lda2, Wh, Wl, ldw2,
                       m0, n0, (c+2)*16, tid);
        const uint32_t* sA  = dsm + (c%3)*GSTG;
        const uint32_t* sAl = sA + GOFF_AL;
        const uint32_t* sW  = sA + GOFF_WH;
        const uint32_t* sWl = sA + GOFF_WL;

        #pragma unroll
        for (int ks = 0; ks < 2; ks++) {
            int kk = ks * 8;
            uint32_t ah[4][4], alr[4][4];
            #pragma unroll
            for (int mi = 0; mi < 4; mi++) {
                int r0 = wm + mi*16 + g;
                ah[mi][0]  = sA [r0*20     + kk+tg];
                ah[mi][1]  = sA [(r0+8)*20 + kk+tg];
                ah[mi][2]  = sA [r0*20     + kk+4+tg];
                ah[mi][3]  = sA [(r0+8)*20 + kk+4+tg];
                alr[mi][0] = sAl[r0*20     + kk+tg];
                alr[mi][1] = sAl[(r0+8)*20 + kk+tg];
                alr[mi][2] = sAl[r0*20     + kk+4+tg];
                alr[mi][3] = sAl[(r0+8)*20 + kk+4+tg];
            }
            #pragma unroll
            for (int nh = 0; nh < 2; nh++) {
                uint32_t bh[2][2], blr[2][2];
                #pragma unroll
                for (int nn = 0; nn < 2; nn++) {
                    int n = wn + (nh*2 + nn)*8 + g;
                    bh[nn][0]  = sW [n*20 + kk+tg];
                    bh[nn][1]  = sW [n*20 + kk+4+tg];
                    blr[nn][0] = sWl[n*20 + kk+tg];
                    blr[nn][1] = sWl[n*20 + kk+4+tg];
                }
                #pragma unroll
                for (int mi = 0; mi < 4; mi++)
                    #pragma unroll
                    for (int nn = 0; nn < 2; nn++) {
                        float* a = acc[mi][nh*2 + nn];
                        mma_bf16(a, ah[mi],  blr[nn]);
                        mma_bf16(a, alr[mi], bh[nn]);
                        mma_bf16(a, ah[mi],  bh[nn]);
                    }
            }
        }
    }

    // epilogue
    int pitch2 = N >> 1;
    #pragma unroll
    for (int mi = 0; mi < 4; mi++) {
        #pragma unroll
        for (int ni = 0; ni < 4; ni++) {
            int row = m0 + wm + mi*16 + g;
            int col = n0 + wn + ni*8 + 2*tg;
            #pragma unroll
            for (int half = 0; half < 2; half++) {
                int rr = row + half*8;
                float vv[2];
                #pragma unroll
                for (int e = 0; e < 2; e++) {
                    int cc = col + e;
                    float v = acc[mi][ni][2*half + e];
                    if (bias)  v += bias[cc];
                    if (bbias) v += bbias[(size_t)(rr/npb)*N + cc];
                    if (bng) {
                        float sc = rsqrtf(bnv[cc] + 1e-5f);
                        v = (v - bnm[cc]) * sc * bng[cc] + bnb[cc];
                    }
                    if (relu) v = fmaxf(v, 0.f);
                    vv[e] = v;
                    if (maxpart) atomMaxF(&smax[cc - n0], v);
                }
                if (Ch) {
                    uint32_t lo;
                    uint32_t hi = packsplit(vv[0], vv[1], lo);
                    Ch[(size_t)rr*pitch2 + (col>>1)] = hi;
                    Cl[(size_t)rr*pitch2 + (col>>1)] = lo;
                }
            }
        }
    }
    if (maxpart) {
        __syncthreads();
        if (tid < 128) maxpart[(size_t)blockIdx.y*N + n0 + tid] = smax[tid];
    }
}

// ----------------------------- column max final -------------------------------
__global__ void colmax_final(const float* __restrict__ part, int nchunks, int nch,
                             float* __restrict__ out) {
    int gid = blockIdx.x*256 + threadIdx.x;
    if (gid >= BATCH*nch) return;
    int b = gid / nch, c = gid % nch;
    float mx = -3.4e38f;
    for (int ch = 0; ch < nchunks; ch++)
        mx = fmaxf(mx, part[((size_t)b*nchunks + ch)*nch + c]);
    out[gid] = mx;
}

// ----------------------------- warp GEMV (16 batches, float4) -----------------
__global__ void gemv16_kernel(const float* __restrict__ Z, int ldz,
                              const float* __restrict__ W, int ldw,
                              int N, int K,
                              const float* __restrict__ bias, int relu,
                              float* __restrict__ out) {
    int warp = (blockIdx.x*blockDim.x + threadIdx.x) >> 5;
    int lane = threadIdx.x & 31;
    if (warp >= N) return;
    float acc[BATCH];
    #pragma unroll
    for (int b = 0; b < BATCH; b++) acc[b] = 0.f;
    const float4* wr4 = (const float4*)(W + (size_t)warp*ldw);
    int K4 = K >> 2;
    for (int i = lane; i < K4; i += 32) {
        float4 w = wr4[i];
        #pragma unroll
        for (int b = 0; b < BATCH; b++) {
            float4 z = *(const float4*)&Z[(size_t)b*ldz + i*4];
            acc[b] += z.x*w.x + z.y*w.y + z.z*w.z + z.w*w.w;
        }
    }
    #pragma unroll
    for (int off = 16; off > 0; off >>= 1)
        #pragma unroll
        for (int b = 0; b < BATCH; b++)
            acc[b] += __shfl_down_sync(0xffffffffu, acc[b], off);
    if (lane == 0) {
        float bv = bias ? bias[warp] : 0.f;
        #pragma unroll
        for (int b = 0; b < BATCH; b++) {
            float v = acc[b] + bv;
            if (relu) v = fmaxf(v, 0.f);
            out[(size_t)b*N + warp] = v;
        }
    }
}

// ----------------------------- chamfer (smem-staged B, float4 quads) ----------
__global__ void chamfer_min_kernel(const float* __restrict__ A, int na,
                                   const float* __restrict__ Bp, int nb_,
                                   float* __restrict__ part) {
    __shared__ float sb[2432*3];
    __shared__ float red[256];
    int chunks = gridDim.x / BATCH;
    int b = blockIdx.x / chunks, ch = blockIdx.x % chunks;
    int t = threadIdx.x;
    const float* bp = Bp + (size_t)b*nb_*3;
    for (int i = t; i < nb_*3; i += 256) sb[i] = bp[i];
    __syncthreads();
    int i = ch*256 + t;
    float s = 0.f;
    if (i < na) {
        const float* ap = A + ((size_t)b*na + i)*3;
        float ax = ap[0], ay = ap[1], az = ap[2];
        const float4* sv4 = (const float4*)sb;
        float mn = 3.0e38f;
        int nq = nb_ >> 2;
        for (int j = 0; j < nq; j++) {
            float4 q0 = sv4[j*3+0];
            float4 q1 = sv4[j*3+1];
            float4 q2 = sv4[j*3+2];
            float dx, dy, dz, d;
            dx = q0.x-ax; dy = q0.y-ay; dz = q0.z-az;
            d = dx*dx + dy*dy + dz*dz; mn = fminf(mn, d);
            dx = q0.w-ax; dy = q1.x-ay; dz = q1.y-az;
            d = dx*dx + dy*dy + dz*dz; mn = fminf(mn, d);
            dx = q1.z-ax; dy = q1.w-ay; dz = q2.x-az;
            d = dx*dx + dy*dy + dz*dz; mn = fminf(mn, d);
            dx = q2.y-ax; dy = q2.z-ay; dz = q2.w-az;
            d = dx*dx + dy*dy + dz*dz; mn = fminf(mn, d);
        }
        s = sqrtf(fmaxf(mn, 1e-12f));
    }
    red[t] = s;
    __syncthreads();
    for (int r = 128; r > 0; r >>= 1) {
        if (t < r) red[t] += red[t+r];
        __syncthreads();
    }
    if (t == 0) part[blockIdx.x] = red[0];
}
__global__ void chamfer_final_kernel(const float* __restrict__ p1, int n1,
                                     const float* __restrict__ p2, int n2,
                                     float w, int tot1, int tot2,
                                     float* __restrict__ slot) {
    double s1 = 0.0, s2 = 0.0;
    for (int i = 0; i < n1; i++) s1 += p1[i];
    for (int i = 0; i < n2; i++) s2 += p2[i];
    *slot = w * 0.5f * (float)(s1/tot1 + s2/tot2);
}

// ----------------------------- huber latent loss ------------------------------
__global__ void huber_kernel(const float* __restrict__ f1, const float* __restrict__ f2,
                             int n, float w, float* __restrict__ slot) {
    int t = threadIdx.x;
    float s = 0.f;
    for (int i = t; i < n; i += 256) {
        float d = f1[i] - f2[i];
        float ad = fabsf(d);
        s += (ad < 1.f) ? 0.5f*d*d : (ad - 0.5f);
    }
    __shared__ float red[256];
    red[t] = s;
    __syncthreads();
    for (int r = 128; r > 0; r >>= 1) {
        if (t < r) red[t] += red[t+r];
        __syncthreads();
    }
    if (t == 0) *slot = w * red[0] / n;
}

// ----------------------------- normals ----------------------------------------
__device__ void eig3_min(double a00, double a01, double a02,
                         double a11, double a12, double a22,
                         double* vx, double* vy, double* vz) {
    double p1 = a01*a01 + a02*a02 + a12*a12;
    double ex = 1, ey = 0, ez = 0;
    if (p1 < 1e-300) {
        if (a00 <= a11 && a00 <= a22) { ex=1; ey=0; ez=0; }
        else if (a11 <= a22)          { ex=0; ey=1; ez=0; }
        else                          { ex=0; ey=0; ez=1; }
    } else {
        double q  = (a00 + a11 + a22) / 3.0;
        double b00 = a00-q, b11 = a11-q, b22 = a22-q;
        double p2 = b00*b00 + b11*b11 + b22*b22 + 2.0*p1;
        double p  = sqrt(p2/6.0);
        double inv = 1.0/p;
        double c00 = b00*inv, c01 = a01*inv, c02 = a02*inv;
        double c11 = b11*inv, c12 = a12*inv, c22 = b22*inv;
        double detB = c00*(c11*c22 - c12*c12) - c01*(c01*c22 - c12*c02) + c02*(c01*c12 - c11*c02);
        double r = detB * 0.5;
        r = fmin(1.0, fmax(-1.0, r));
        double phi = acos(r) / 3.0;
        double l1 = q + 2.0*p*cos(phi);
        double l3 = q + 2.0*p*cos(phi + 2.0943951023931953);
        double l2 = 3.0*q - l1 - l3;
        double A1[3][3] = {{a00-l1, a01, a02}, {a01, a11-l1, a12}, {a02, a12, a22-l1}};
        double A2[3][3] = {{a00-l2, a01, a02}, {a01, a11-l2, a12}, {a02, a12, a22-l2}};
        double Mby[3][3];
        for (int i = 0; i < 3; i++)
            for (int j = 0; j < 3; j++)
                Mby[i][j] = A1[i][0]*A2[0][j] + A1[i][1]*A2[1][j] + A1[i][2]*A2[2][j];
        double bestn = -1.0;
        for (int j = 0; j < 3; j++) {
            double nx = Mby[0][j], ny = Mby[1][j], nz = Mby[2][j];
            double nn = nx*nx + ny*ny + nz*nz;
            if (nn > bestn) { bestn = nn; ex = nx; ey = ny; ez = nz; }
        }
        if (bestn < 1e-200) {
            double C[3][3] = {{a00-l3, a01, a02}, {a01, a11-l3, a12}, {a02, a12, a22-l3}};
            bestn = -1.0;
            int pairs[3][2] = {{0,1},{0,2},{1,2}};
            for (int pp = 0; pp < 3; pp++) {
                int r0 = pairs[pp][0], r1 = pairs[pp][1];
                double nx = C[r0][1]*C[r1][2] - C[r0][2]*C[r1][1];
                double ny = C[r0][2]*C[r1][0] - C[r0][0]*C[r1][2];
                double nz = C[r0][0]*C[r1][1] - C[r0][1]*C[r1][0];
                double nn = nx*nx + ny*ny + nz*nz;
                if (nn > bestn) { bestn = nn; ex = nx; ey = ny; ez = nz; }
            }
            if (bestn < 1e-200) { ex = 1; ey = 0; ez = 0; }
        }
    }
    double nrm = sqrt(ex*ex + ey*ey + ez*ez);
    double invn = 1.0 / nrm;
    *vx = ex*invn; *vy = ey*invn; *vz = ez*invn;
}

__global__ void normals_kernel(const float* __restrict__ pred,
                               const int* __restrict__ idx,
                               float* __restrict__ nrm) {
    int gid = blockIdx.x*256 + threadIdx.x;
    if (gid >= BATCH*NPTS) return;
    int b = gid / NPTS;
    const int* ip = idx + (size_t)gid*NBH;
    const float* base = pred + (size_t)b*NPTS*3;
    float px[NBH], py[NBH], pz[NBH];
    float sx = 0.f, sy = 0.f, sz = 0.f;
    #pragma unroll 4
    for (int k = 0; k < NBH; k++) {
        const float* p = base + (size_t)ip[k]*3;
        px[k] = p[0]; py[k] = p[1]; pz[k] = p[2];
        sx += px[k]; sy += py[k]; sz += pz[k];
    }
    float mx = sx*(1.f/NBH), my = sy*(1.f/NBH), mz = sz*(1.f/NBH);
    float cxx=0.f, cxy=0.f, cxz=0.f, cyy=0.f, cyz=0.f, czz=0.f;
    #pragma unroll 4
    for (int k = 0; k < NBH; k++) {
        float dx = px[k]-mx, dy = py[k]-my, dz = pz[k]-mz;
        cxx += dx*dx; cxy += dx*dy; cxz += dx*dz;
        cyy += dy*dy; cyz += dy*dz; czz += dz*dz;
    }
    float inv = 1.f/NBH;
    double vx, vy, vz;
    eig3_min((double)(cxx*inv), (double)(cxy*inv), (double)(cxz*inv),
             (double)(cyy*inv), (double)(cyz*inv), (double)(czz*inv),
             &vx, &vy, &vz);
    const float* xp = pred + (size_t)gid*3;
    double proj = 0.0;
    #pragma unroll 4
    for (int k = 0; k < NBH; k++)
        proj += (px[k]-xp[0])*vx + (py[k]-xp[1])*vy + (pz[k]-xp[2])*vz;
    double sgn = (proj >= 0.0) ? 1.0 : -1.0;
    nrm[(size_t)gid*3+0] = (float)(vx*sgn);
    nrm[(size_t)gid*3+1] = (float)(vy*sgn);
    nrm[(size_t)gid*3+2] = (float)(vz*sgn);
}

__global__ void manifold_kernel(const float* __restrict__ nrm,
                                const int* __restrict__ idx,
                                float* __restrict__ outstd) {
    int gid = blockIdx.x*256 + threadIdx.x;
    if (gid >= BATCH*NPTS) return;
    int b = gid / NPTS;
    const int* ip = idx + (size_t)gid*NBH;
    const float* base = nrm + (size_t)b*NPTS*3;
    const float* a = base + (size_t)ip[0]*3;
    float ax = a[0], ay = a[1], az = a[2];
    float an = fmaxf(sqrtf(ax*ax + ay*ay + az*az), 1e-6f);
    float vals[SUP];
    #pragma unroll
    for (int j = 0; j < SUP; j++) {
        const float* nj = base + (size_t)ip[j]*3;
        float nn = fmaxf(sqrtf(nj[0]*nj[0] + nj[1]*nj[1] + nj[2]*nj[2]), 1e-6f);
        float cosv = (ax*nj[0] + ay*nj[1] + az*nj[2]) / (an * nn);
        vals[j] = 1.f - cosv;
    }
    float mean = 0.f;
    #pragma unroll
    for (int j = 0; j < SUP; j++) mean += vals[j];
    mean /= SUP;
    float var = 0.f;
    #pragma unroll
    for (int j = 0; j < SUP; j++) { float d = vals[j]-mean; var += d*d; }
    var /= (SUP - 1);
    outstd[gid] = sqrtf(fmaxf(var, 0.f));
}

__global__ void mean_kernel(const float* __restrict__ in, int n, float w,
                            float* __restrict__ slot) {
    int t = threadIdx.x;
    float s = 0.f;
    for (int i = t; i < n; i += 256) s += in[i];
    __shared__ float red[256];
    red[t] = s;
    __syncthreads();
    for (int r = 128; r > 0; r >>= 1) {
        if (t < r) red[t] += red[t+r];
        __syncthreads();
    }
    if (t == 0) *slot = w * red[0] / n;
}

__global__ void final_kernel(const float* __restrict__ loss, float* __restrict__ out) {
    out[0] = loss[0] + loss[1] + loss[2] + loss[3];
    out[1] = loss[0];
    out[2] = loss[1];
    out[3] = loss[2];
    out[4] = loss[3];
}

// ----------------------------- host-side orchestration -----------------------
static void* sym(const void* symbol) {
    void* p = nullptr;
    cudaGetSymbolAddress(&p, symbol);
    return p;
}

struct Params {
    const float *W1,*b1,*g1,*be1,*m1,*v1,*W2,*b2,*W3,*b3,*g2,*be2,*m2,*v2,*W4,*b4;
    const float *D1W,*D1b,*D2W,*D2b,*D3W,*D3b,*D4W,*D4b;
};

#define GEMM_SMEM (3*GSTG*4)

static void run_encoder(const float* x, int npts, float* feat_out, const Params& P,
                        float* gmax, float* gb, float* cmpart, cudaStream_t st) {
    int M = BATCH * npts;
    int nchunks = npts / 256;
    uint32_t* h1h = (uint32_t*)sym(g_h1h); uint32_t* h1l = (uint32_t*)sym(g_h1l);
    uint32_t* h2h = (uint32_t*)sym(g_h2h); uint32_t* h2l = (uint32_t*)sym(g_h2l);
    uint32_t* h4h = (uint32_t*)sym(g_h4h); uint32_t* h4l = (uint32_t*)sym(g_h4l);
    uint32_t* w2h = (uint32_t*)sym(g_w2h); uint32_t* w2l = (uint32_t*)sym(g_w2l);
    uint32_t* w3h = (uint32_t*)sym(g_w3h); uint32_t* w3l = (uint32_t*)sym(g_w3l);
    uint32_t* w4h = (uint32_t*)sym(g_w4h); uint32_t* w4l = (uint32_t*)sym(g_w4l);

    layer1_kernel<<<(M*64 + 255)/256, 256, 0, st>>>(x, P.W1, P.b1, P.g1, P.be1, P.m1, P.v1,
                                                    h1h, h1l, M);
    {
        dim3 grid(256/128, M/256);
        gemm_tc<<<grid, 512, GEMM_SMEM, st>>>(h1h, h1l, 64, w2h, w2l, 64, M, 256, 128,
                               P.b2, nullptr, 1, nullptr, nullptr, nullptr, nullptr, 0,
                               h2h, h2l, cmpart);
    }
    colmax_final<<<(BATCH*256 + 255)/256, 256, 0, st>>>(cmpart, nchunks, 256, gmax);
    gemv16_kernel<<<(512 + 7)/8, 256, 0, st>>>(gmax, 256, P.W3, 512, 512, 256, P.b3, 0, gb);
    {
        dim3 grid(512/128, M/256);
        gemm_tc<<<grid, 512, GEMM_SMEM, st>>>(h2h, h2l, 128, w3h, w3l, 128, M, 512, 256,
                               nullptr, gb, npts, P.g2, P.be2, P.m2, P.v2, 1,
                               h4h, h4l, nullptr);
    }
    {
        dim3 grid(1024/128, M/256);
        gemm_tc<<<grid, 512, GEMM_SMEM, st>>>(h4h, h4l, 256, w4h, w4l, 256, M, 1024, 512,
                               P.b4, nullptr, 1, nullptr, nullptr, nullptr, nullptr, 0,
                               nullptr, nullptr, cmpart);
    }
    colmax_final<<<(BATCH*1024 + 255)/256, 256, 0, st>>>(cmpart, nchunks, 1024, feat_out);
}

extern "C" void kernel_launch(void* const* d_in, const int* in_sizes, int n_in,
                              void* d_out, int out_size) {
    const float* pts = (const float*)d_in[0];
    Params P;
    P.W1  = (const float*)d_in[1];  P.b1  = (const float*)d_in[2];
    P.g1  = (const float*)d_in[3];  P.be1 = (const float*)d_in[4];
    P.m1  = (const float*)d_in[5];  P.v1  = (const float*)d_in[6];
    P.W2  = (const float*)d_in[7];  P.b2  = (const float*)d_in[8];
    P.W3  = (const float*)d_in[9];  P.b3  = (const float*)d_in[10];
    P.g2  = (const float*)d_in[11]; P.be2 = (const float*)d_in[12];
    P.m2  = (const float*)d_in[13]; P.v2  = (const float*)d_in[14];
    P.W4  = (const float*)d_in[15]; P.b4  = (const float*)d_in[16];
    P.D1W = (const float*)d_in[17]; P.D1b = (const float*)d_in[18];
    P.D2W = (const float*)d_in[19]; P.D2b = (const float*)d_in[20];
    P.D3W = (const float*)d_in[21]; P.D3b = (const float*)d_in[22];
    P.D4W = (const float*)d_in[23]; P.D4b = (const float*)d_in[24];
    float* out = (float*)d_out;

    static cudaStream_t s1 = nullptr, s2 = nullptr, s3 = nullptr;
    static cudaEvent_t evStart = nullptr, evSplit = nullptr, evPred = nullptr;
    static cudaEvent_t evA = nullptr, evB = nullptr, evD = nullptr;
    if (!s1) {
        cudaStreamCreateWithFlags(&s1, cudaStreamNonBlocking);
        cudaStreamCreateWithFlags(&s2, cudaStreamNonBlocking);
        cudaStreamCreateWithFlags(&s3, cudaStreamNonBlocking);
        cudaEventCreateWithFlags(&evStart, cudaEventDisableTiming);
        cudaEventCreateWithFlags(&evSplit, cudaEventDisableTiming);
        cudaEventCreateWithFlags(&evPred,  cudaEventDisableTiming);
        cudaEventCreateWithFlags(&evA, cudaEventDisableTiming);
        cudaEventCreateWithFlags(&evB, cudaEventDisableTiming);
        cudaEventCreateWithFlags(&evD, cudaEventDisableTiming);
        cudaFuncSetAttribute(gemm_tc, cudaFuncAttributeMaxDynamicSharedMemorySize, GEMM_SMEM);
    }

    int*   fps    = (int*)  sym(g_fps);
    float* center = (float*)sym(g_center);
    int*   knnc   = (int*)  sym(g_knnc);
    float* reb0   = (float*)sym(g_reb0);
    float* reb1   = (float*)sym(g_reb1);
    float* encin2 = (float*)sym(g_encin2);
    float* gmax   = (float*)sym(g_gmax);
    float* gb     = (float*)sym(g_gb);
    float* cmpart = (float*)sym(g_cmpart);
    float* feat   = (float*)sym(g_feat);
    float* feat2  = (float*)sym(g_feat2);
    float* dec1   = (float*)sym(g_dec1);
    float* dec2   = (float*)sym(g_dec2);
    float* dec3   = (float*)sym(g_dec3);
    float* pred   = (float*)sym(g_pred);
    int*   knngA  = (int*)  sym(g_knngA);
    int*   knngB  = (int*)  sym(g_knngB);
    int*   knngC  = (int*)  sym(g_knngC);
    float* gathA  = (float*)sym(g_gathA);
    float* gathB  = (float*)sym(g_gathB);
    int*   knnp   = (int*)  sym(g_knnp);
    float* nrm    = (float*)sym(g_normals);
    float* stdbuf = (float*)sym(g_std);
    float* partA1 = (float*)sym(g_partA1);
    float* partA2 = (float*)sym(g_partA2);
    float* partB1 = (float*)sym(g_partB1);
    float* partB2 = (float*)sym(g_partB2);
    float* loss   = (float*)sym(g_loss);

    // fork: weight splitting on s1, concurrent with FPS/grouping on main
    cudaEventRecord(evStart, 0);
    cudaStreamWaitEvent(s1, evStart, 0);
    splitw_kernel<<<(256*64 + 255)/256, 256, 0, s1>>>(P.W2, 128, 0, 256*64, 64,
                                               (uint32_t*)sym(g_w2h), (uint32_t*)sym(g_w2l));
    splitw_kernel<<<(512*128 + 255)/256, 256, 0, s1>>>(P.W3, 512, 256, 512*128, 128,
                                               (uint32_t*)sym(g_w3h), (uint32_t*)sym(g_w3l));
    splitw_kernel<<<(1024*256 + 255)/256, 256, 0, s1>>>(P.W4, 512, 0, 1024*256, 256,
                                               (uint32_t*)sym(g_w4h), (uint32_t*)sym(g_w4l));
    cudaEventRecord(evSplit, s1);

    // 1. FPS + center + grouping (main)
    fps_kernel<<<BATCH, 512>>>(pts, fps);
    gather3_kernel<<<(BATCH*NG + 255)/256, 256>>>(pts, NPTS, fps, NG, NG, center);
    knn_kernel<<<BATCH*NG, 256>>>(center, NG, NG, pts, NPTS, GS, knnc);
    gather3_kernel<<<(BATCH*2048 + 255)/256, 256>>>(pts, NPTS, knnc, NG*GS, 2048, reb0);
    gather3_kernel<<<(BATCH*1024 + 255)/256, 256>>>(pts, NPTS, knnc + O1*GS, NG*GS, 1024, reb1);

    // join splits before encoder GEMMs
    cudaStreamWaitEvent(0, evSplit, 0);

    // 2. encoder pass A + decoder (main)
    run_encoder(reb0, 2048, feat, P, gmax, gb, cmpart, 0);
    gemv16_kernel<<<2048/8, 256>>>(feat, 1024, P.D1W, 1024, 2048, 1024, P.D1b, 1, dec1);
    gemv16_kernel<<<2048/8, 256>>>(dec1, 2048, P.D2W, 2048, 2048, 2048, P.D2b, 1, dec2);
    gemv16_kernel<<<2048/8, 256>>>(dec2, 2048, P.D3W, 2048, 2048, 2048, P.D3b, 1, dec3);
    gemv16_kernel<<<6144/8, 256>>>(dec3, 2048, P.D4W, 2048, 6144, 2048, P.D4b, 0, pred);

    // fork after pred
    cudaEventRecord(evPred, 0);
    cudaStreamWaitEvent(s1, evPred, 0);
    cudaStreamWaitEvent(s2, evPred, 0);
    cudaStreamWaitEvent(s3, evPred, 0);

    // branch A (s1): l_recon
    knn_kernel<<<BATCH*64, 256, 0, s1>>>(center, NG, 64, pred, NPTS, NBRK, knngA);
    gather3_kernel<<<(BATCH*2432 + 255)/256, 256, 0, s1>>>(pred, NPTS, knngA, 64*NBRK, 2432, gathA);
    chamfer_min_kernel<<<BATCH*8, 256, 0, s1>>>(reb0, 2048, gathA, 2432, partA1);
    chamfer_min_kernel<<<BATCH*10, 256, 0, s1>>>(gathA, 2432, reb0, 2048, partA2);
    chamfer_final_kernel<<<1, 1, 0, s1>>>(partA1, BATCH*8, partA2, BATCH*10, 1.0f,
                                          BATCH*2048, BATCH*2432, loss + 0);
    cudaEventRecord(evA, s1);

    // branch B (s2): l_match
    knn_kernel<<<BATCH*32, 256, 0, s2>>>(center + O1*3, NG, 32, pred, NPTS, NBRK, knngB);
    gather3_kernel<<<(BATCH*1216 + 255)/256, 256, 0, s2>>>(pred, NPTS, knngB, 32*NBRK, 1216, gathB);
    chamfer_min_kernel<<<BATCH*4, 256, 0, s2>>>(reb1, 1024, gathB, 1216, partB1);
    chamfer_min_kernel<<<BATCH*5, 256, 0, s2>>>(gathB, 1216, reb1, 1024, partB2);
    chamfer_final_kernel<<<1, 1, 0, s2>>>(partB1, BATCH*4, partB2, BATCH*5, 1.0f,
                                          BATCH*1024, BATCH*1216, loss + 1);
    cudaEventRecord(evB, s2);

    // branch D (s3): l_man (heaviest independent chain)
    knn_kernel<<<BATCH*NPTS, 256, 0, s3>>>(pred, NPTS, NPTS, pred, NPTS, NBH, knnp);
    normals_kernel<<<(BATCH*NPTS + 255)/256, 256, 0, s3>>>(pred, knnp, nrm);
    manifold_kernel<<<(BATCH*NPTS + 255)/256, 256, 0, s3>>>(nrm, knnp, stdbuf);
    mean_kernel<<<1, 256, 0, s3>>>(stdbuf, BATCH*NPTS, 0.1f, loss + 3);
    cudaEventRecord(evD, s3);

    // branch C (main): l_latent encoder pass
    knn_kernel<<<BATCH*32, 256>>>(center + O2*3, NG, 32, pred, NPTS, GS, knngC);
    gather3_kernel<<<(BATCH*1024 + 255)/256, 256>>>(pred, NPTS, knngC, 32*GS, 1024, encin2);
    run_encoder(encin2, 1024, feat2, P, gmax, gb, cmpart, 0);
    huber_kernel<<<1, 256>>>(feat, feat2, BATCH*FEATD, 1.0f, loss + 2);

    // join all branches, then final
    cudaStreamWaitEvent(0, evA, 0);
    cudaStreamWaitEvent(0, evB, 0);
    cudaStreamWaitEvent(0, evD, 0);
    final_kernel<<<1, 1>>>(loss, out);
}

// round 13
// speedup vs baseline: 1.3962x; 1.3962x over previous
#include <cuda_runtime.h>
#include <cuda_bf16.h>
#include <math.h>
#include <stdint.h>

#define BATCH 16
#define NPTS 2048
#define NG 128
#define GS 32
#define O1 64
#define O2 96
#define FEATD 1024
#define NBRK 38
#define SUP 8
#define NBH 32

// ----------------------------- scratch (static device globals) ---------------
__device__ int   g_fps[BATCH*NG];
__device__ float g_center[BATCH*NG*3];
__device__ int   g_knnc[BATCH*NG*GS];
__device__ __align__(16) float g_reb0[BATCH*2048*3];
__device__ __align__(16) float g_reb1[BATCH*1024*3];
__device__ __align__(16) float g_encin2[BATCH*1024*3];
__device__ __align__(16) float g_gmax[BATCH*256];
__device__ __align__(16) float g_gb[BATCH*512];
__device__ float g_cmpart[256*1024];
__device__ __align__(16) float g_feat[BATCH*1024];
__device__ __align__(16) float g_feat2[BATCH*1024];
__device__ __align__(16) float g_dec1[BATCH*2048];
__device__ __align__(16) float g_dec2[BATCH*2048];
__device__ __align__(16) float g_dec3[BATCH*2048];
__device__ __align__(16) float g_pred[BATCH*2048*3];
__device__ int   g_knngA[BATCH*64*38];
__device__ int   g_knngB[BATCH*32*38];
__device__ int   g_knngC[BATCH*32*32];
__device__ __align__(16) float g_gathA[BATCH*2432*3];
__device__ __align__(16) float g_gathB[BATCH*1216*3];
__device__ int   g_knnp[BATCH*2048*32];
__device__ float g_normals[BATCH*2048*3];
__device__ float g_std[BATCH*2048];
__device__ float g_partA1[128];
__device__ float g_partA2[160];
__device__ float g_partB1[64];
__device__ float g_partB2[80];
__device__ float g_loss[4];

// split (bf16 hi/lo packed pairs) buffers
__device__ __align__(16) uint32_t g_w2h[256*64],    g_w2l[256*64];
__device__ __align__(16) uint32_t g_w3h[512*128],   g_w3l[512*128];
__device__ __align__(16) uint32_t g_w4h[1024*256],  g_w4l[1024*256];
__device__ __align__(16) uint32_t g_h1h[BATCH*2048*64],  g_h1l[BATCH*2048*64];
__device__ __align__(16) uint32_t g_h2h[BATCH*2048*128], g_h2l[BATCH*2048*128];
__device__ __align__(16) uint32_t g_h4h[BATCH*2048*256], g_h4l[BATCH*2048*256];

// ----------------------------- helpers ---------------------------------------
__device__ __forceinline__ uint32_t packsplit(float a, float b, uint32_t& lo) {
    __nv_bfloat16 ha = __float2bfloat16_rn(a);
    __nv_bfloat16 hb = __float2bfloat16_rn(b);
    __nv_bfloat16 la = __float2bfloat16_rn(a - __bfloat162float(ha));
    __nv_bfloat16 lb = __float2bfloat16_rn(b - __bfloat162float(hb));
    __nv_bfloat162 l2 = __halves2bfloat162(la, lb);
    __nv_bfloat162 h2 = __halves2bfloat162(ha, hb);
    lo = *(uint32_t*)&l2;
    return *(uint32_t*)&h2;
}
__device__ __forceinline__ void mma_bf16(float* d, const uint32_t* a, const uint32_t* b) {
    asm volatile("mma.sync.aligned.m16n8k16.row.col.f32.bf16.bf16.f32 "
        "{%0,%1,%2,%3}, {%4,%5,%6,%7}, {%8,%9}, {%0,%1,%2,%3};"
        : "+f"(d[0]), "+f"(d[1]), "+f"(d[2]), "+f"(d[3])
        : "r"(a[0]), "r"(a[1]), "r"(a[2]), "r"(a[3]), "r"(b[0]), "r"(b[1]));
}
__device__ __forceinline__ void atomMaxF(float* a, float v) {
    if (v >= 0.f) atomicMax((int*)a, __float_as_int(v));
    else atomicMin((unsigned int*)a, __float_as_uint(v));
}
__device__ __forceinline__ uint32_t s2a(const void* p) {
    return (uint32_t)__cvta_generic_to_shared(p);
}
__device__ __forceinline__ void cpasync16(uint32_t saddr, const void* g) {
    asm volatile("cp.async.cg.shared.global [%0], [%1], 16;" :: "r"(saddr), "l"(g));
}

// ----------------------------- FPS (512 thr, 1 barrier/round) -----------------
__global__ void fps_kernel(const float* __restrict__ pts, int* __restrict__ out) {
    __shared__ float sx[NPTS], sy[NPTS], sz[NPTS];
    __shared__ unsigned long long slot[NG];
    int b = blockIdx.x, t = threadIdx.x, lane = t & 31;
    const float* p = pts + (size_t)b*NPTS*3;
    for (int i = t; i < NPTS; i += 512) {
        sx[i] = p[3*i]; sy[i] = p[3*i+1]; sz[i] = p[3*i+2];
    }
    for (int i = t; i < NG; i += 512) slot[i] = 0ULL;
    float px[4], py[4], pz[4], dv[4];
    #pragma unroll
    for (int r = 0; r < 4; r++) {
        int i = t + r*512;
        px[r] = p[3*i]; py[r] = p[3*i+1]; pz[r] = p[3*i+2];
        dv[r] = 1e10f;
    }
    __syncthreads();
    int far = 0;
    for (int g = 0; g < NG; g++) {
        if (t == 0) out[b*NG + g] = far;
        float cx = sx[far], cy = sy[far], cz = sz[far];
        float bv = 0.f; int bi = 0;
        #pragma unroll
        for (int r = 0; r < 4; r++) {
            float dx = px[r]-cx, dy = py[r]-cy, dz = pz[r]-cz;
            float d = dx*dx + dy*dy + dz*dz;
            float m = fminf(dv[r], d);
            dv[r] = m;
            if (r == 0) { bv = m; bi = t; }
            else if (m > bv) { bv = m; bi = t + r*512; }
        }
        #pragma unroll
        for (int off = 16; off > 0; off >>= 1) {
            float ov = __shfl_down_sync(0xffffffffu, bv, off);
            int   oi = __shfl_down_sync(0xffffffffu, bi, off);
            if (ov > bv || (ov == bv && oi < bi)) { bv = ov; bi = oi; }
        }
        if (lane == 0) {
            unsigned long long key =
                ((unsigned long long)__float_as_uint(bv) << 32) |
                (unsigned long long)(unsigned)(~bi);
            atomicMax(&slot[g], key);
        }
        __syncthreads();
        far = (int)(~(unsigned)(slot[g] & 0xffffffffu));
    }
}

// ----------------------------- gather ----------------------------------------
__global__ void gather3_kernel(const float* __restrict__ db, int dbstride,
                               const int* __restrict__ idx, int idxstride,
                               int cnt, float* __restrict__ out) {
    int gid = blockIdx.x*blockDim.x + threadIdx.x;
    if (gid >= BATCH*cnt) return;
    int b = gid / cnt, i = gid % cnt;
    int j = idx[b*idxstride + i];
    const float* s = db + ((size_t)b*dbstride + j)*3;
    float* o = out + (size_t)gid*3;
    o[0] = s[0]; o[1] = s[1]; o[2] = s[2];
}

// ----------------------------- kNN (register-cached incremental, round-5) -----
__global__ void knn_kernel(const float* __restrict__ q, int qstride, int nq,
                           const float* __restrict__ db, int dbstride,
                           int k, int* __restrict__ out) {
    __shared__ float swv[8];
    __shared__ int   swi[8];
    __shared__ int   swin;
    int b = blockIdx.x / nq, qi = blockIdx.x % nq;
    int t = threadIdx.x, lane = t & 31, wid = t >> 5;
    const float* qp = q + ((size_t)b*qstride + qi)*3;
    float qx = qp[0], qy = qp[1], qz = qp[2];
    const float* dp = db + (size_t)b*dbstride*3;
    float dv[8];
    #pragma unroll
    for (int r = 0; r < 8; r++) {
        int i = t + r*256;
        float dx = dp[3*i]-qx, dy = dp[3*i+1]-qy, dz = dp[3*i+2]-qz;
        dv[r] = dx*dx + dy*dy + dz*dz;
    }
    float lmv = 3.9e38f; int lmi = (1<<30);
    #pragma unroll
    for (int r = 0; r < 8; r++)
        if (dv[r] < lmv) { lmv = dv[r]; lmi = t + r*256; }
    {
        float rv = lmv; int ri = lmi;
        #pragma unroll
        for (int off = 16; off > 0; off >>= 1) {
            float ov = __shfl_down_sync(0xffffffffu, rv, off);
            int   oi = __shfl_down_sync(0xffffffffu, ri, off);
            if (ov < rv || (ov == rv && oi < ri)) { rv = ov; ri = oi; }
        }
        if (lane == 0) { swv[wid] = rv; swi[wid] = ri; }
    }
    __syncthreads();
    int* op = out + ((size_t)b*nq + qi)*k;
    for (int s = 0; s < k; s++) {
        if (wid == 0) {
            float rv = (lane < 8) ? swv[lane] : 3.9e38f;
            int   ri = (lane < 8) ? swi[lane] : (1<<30);
            #pragma unroll
            for (int off = 4; off > 0; off >>= 1) {
                float ov = __shfl_down_sync(0xffffffffu, rv, off);
                int   oi = __shfl_down_sync(0xffffffffu, ri, off);
                if (ov < rv || (ov == rv && oi < ri)) { rv = ov; ri = oi; }
            }
            if (lane == 0) { op[s] = ri; swin = ri; }
        }
        __syncthreads();
        int win = swin;
        int owner = win & 255;
        if (t == owner) {
            int r0 = win >> 8;
            #pragma unroll
            for (int r = 0; r < 8; r++) if (r == r0) dv[r] = 3.9e38f;
            lmv = 3.9e38f; lmi = (1<<30);
            #pragma unroll
            for (int r = 0; r < 8; r++)
                if (dv[r] < lmv) { lmv = dv[r]; lmi = t + r*256; }
        }
        if ((t >> 5) == (owner >> 5)) {
            float rv = lmv; int ri = lmi;
            #pragma unroll
            for (int off = 16; off > 0; off >>= 1) {
                float ov = __shfl_down_sync(0xffffffffu, rv, off);
                int   oi = __shfl_down_sync(0xffffffffu, ri, off);
                if (ov < rv || (ov == rv && oi < ri)) { rv = ov; ri = oi; }
            }
            if (lane == 0) { swv[wid] = rv; swi[wid] = ri; }
        }
        __syncthreads();
    }
}

// ----------------------------- weight splitting -------------------------------
__global__ void splitw_kernel(const float* __restrict__ W, int ld, int coloff,
                              int total, int cols2,
                              uint32_t* __restrict__ Oh, uint32_t* __restrict__ Ol) {
    int gid = blockIdx.x*256 + threadIdx.x;
    if (gid >= total) return;
    int n = gid / cols2, j = gid % cols2;
    float a = W[(size_t)n*ld + coloff + 2*j];
    float b = W[(size_t)n*ld + coloff + 2*j + 1];
    uint32_t lo;
    uint32_t hi = packsplit(a, b, lo);
    Oh[gid] = hi; Ol[gid] = lo;
}

// ----------------------------- encoder layer 1 (K=3), split output ------------
__global__ void layer1_kernel(const float* __restrict__ x,
                              const float* __restrict__ W1, const float* __restrict__ b1,
                              const float* __restrict__ g1, const float* __restrict__ be1,
                              const float* __restrict__ m1, const float* __restrict__ v1,
                              uint32_t* __restrict__ h1h, uint32_t* __restrict__ h1l,
                              int M) {
    int gid = blockIdx.x*256 + threadIdx.x;
    if (gid >= M*64) return;
    int m = gid >> 6, j = gid & 63;
    const float* xp = x + (size_t)m*3;
    float x0 = xp[0], x1 = xp[1], x2 = xp[2];
    float v[2];
    #pragma unroll
    for (int h = 0; h < 2; h++) {
        int n = 2*j + h;
        float acc = x0*W1[n*3] + x1*W1[n*3+1] + x2*W1[n*3+2] + b1[n];
        float sc = rsqrtf(v1[n] + 1e-5f);
        float val = (acc - m1[n]) * sc * g1[n] + be1[n];
        v[h] = fmaxf(val, 0.f);
    }
    uint32_t lo;
    uint32_t hi = packsplit(v[0], v[1], lo);
    h1h[gid] = hi; h1l[gid] = lo;
}

// ----------------------------- tensor-core GEMM (3x bf16 split, cp.async) -----
#define GSTG 15360         // u32 per stage
#define GOFF_AL 5120
#define GOFF_WH 10240
#define GOFF_WL 12800

__device__ __forceinline__ void gemm_issue(uint32_t* stg,
        const uint32_t* Ah, const uint32_t* Al, int lda2,
        const uint32_t* Wh, const uint32_t* Wl, int ldw2,
        int m0, int n0, int k2, int tid) {
    #pragma unroll
    for (int p = 0; p < 2; p++) {
        int idx = tid + p*512;
        int r = idx >> 2, sl = idx & 3;
        size_t go = (size_t)(m0 + r)*lda2 + k2 + sl*4;
        cpasync16(s2a(stg + r*20 + sl*4), Ah + go);
        cpasync16(s2a(stg + GOFF_AL + r*20 + sl*4), Al + go);
    }
    {
        int idx = tid;
        int r = idx >> 2, sl = idx & 3;
        size_t go = (size_t)(n0 + r)*ldw2 + k2 + sl*4;
        cpasync16(s2a(stg + GOFF_WH + r*20 + sl*4), Wh + go);
        cpasync16(s2a(stg + GOFF_WL + r*20 + sl*4), Wl + go);
    }
    asm volatile("cp.async.commit_group;" ::: "memory");
}

__global__ __launch_bounds__(512, 1) void gemm_tc(
        const uint32_t* __restrict__ Ah, const uint32_t* __restrict__ Al, int lda2,
        const uint32_t* __restrict__ Wh, const uint32_t* __restrict__ Wl, int ldw2,
        int M, int N, int K,
        const float* __restrict__ bias,
        const float* __restrict__ bbias, int npb,
        const float* __restrict__ bng, const float* __restrict__ bnb,
        const float* __restrict__ bnm, const float* __restrict__ bnv,
        int relu,
        uint32_t* __restrict__ Ch, uint32_t* __restrict__ Cl,
        float* __restrict__ maxpart) {
    extern __shared__ uint32_t dsm[];
    __shared__ float smax[128];
    int tid = threadIdx.x;
    int warp = tid >> 5, lane = tid & 31;
    int wm = (warp >> 2) * 64, wn = (warp & 3) * 32;
    int m0 = blockIdx.y * 256, n0 = blockIdx.x * 128;
    int g = lane >> 2, tg = lane & 3;

    if (maxpart && tid < 128) smax[tid] = -3.4e38f;

    float acc[4][4][4];
    #pragma unroll
    for (int mi = 0; mi < 4; mi++)
        #pragma unroll
        for (int ni = 0; ni < 4; ni++)
            #pragma unroll
            for (int r = 0; r < 4; r++) acc[mi][ni][r] = 0.f;

    int nch = K / 32;
    gemm_issue(dsm, Ah, Al, lda2, Wh, Wl, ldw2, m0, n0, 0, tid);
    if (nch > 1) gemm_issue(dsm + GSTG, Ah, Al, lda2, Wh, Wl, ldw2, m0, n0, 16, tid);

    for (int c = 0; c < nch; c++) {
        if (c < nch - 1) asm volatile("cp.async.wait_group 1;" ::: "memory");
        else             asm volatile("cp.async.wait_group 0;" ::: "memory");
        __syncthreads();
        if (c + 2 < nch)
            gemm_issue(dsm + ((c+2)%3)*GSTG, Ah, Al, lda2, Wh, Wl, ldw2,
                       m0, n0, (c+2)*16, tid);
        const uint32_t* sA  = dsm + (c%3)*GSTG;
        const uint32_t* sAl = sA + GOFF_AL;
        const uint32_t* sW  = sA + GOFF_WH;
        const uint32_t* sWl = sA + GOFF_WL;

        #pragma unroll
        for (int ks = 0; ks < 2; ks++) {
            int kk = ks * 8;
            uint32_t ah[4][4], alr[4][4];
            #pragma unroll
            for (int mi = 0; mi < 4; mi++) {
                int r0 = wm + mi*16 + g;
                ah[mi][0]  = sA [r0*20     + kk+tg];
                ah[mi][1]  = sA [(r0+8)*20 + kk+tg];
                ah[mi][2]  = sA [r0*20     + kk+4+tg];
                ah[mi][3]  = sA [(r0+8)*20 + kk+4+tg];
                alr[mi][0] = sAl[r0*20     + kk+tg];
                alr[mi][1] = sAl[(r0+8)*20 + kk+tg];
                alr[mi][2] = sAl[r0*20     + kk+4+tg];
                alr[mi][3] = sAl[(r0+8)*20 + kk+4+tg];
            }
            #pragma unroll
            for (int nh = 0; nh < 2; nh++) {
                uint32_t bh[2][2], blr[2][2];
                #pragma unroll
                for (int nn = 0; nn < 2; nn++) {
                    int n = wn + (nh*2 + nn)*8 + g;
                    bh[nn][0]  = sW [n*20 + kk+tg];
                    bh[nn][1]  = sW [n*20 + kk+4+tg];
                    blr[nn][0] = sWl[n*20 + kk+tg];
                    blr[nn][1] = sWl[n*20 + kk+4+tg];
                }
                #pragma unroll
                for (int mi = 0; mi < 4; mi++)
                    #pragma unroll
                    for (int nn = 0; nn < 2; nn++) {
                        float* a = acc[mi][nh*2 + nn];
                        mma_bf16(a, ah[mi],  blr[nn]);
                        mma_bf16(a, alr[mi], bh[nn]);
                        mma_bf16(a, ah[mi],  bh[nn]);
                    }
            }
        }
    }

    // epilogue
    int pitch2 = N >> 1;
    #pragma unroll
    for (int mi = 0; mi < 4; mi++) {
        #pragma unroll
        for (int ni = 0; ni < 4; ni++) {
            int row = m0 + wm + mi*16 + g;
            int col = n0 + wn + ni*8 + 2*tg;
            #pragma unroll
            for (int half = 0; half < 2; half++) {
                int rr = row + half*8;
                float vv[2];
                #pragma unroll
                for (int e = 0; e < 2; e++) {
                    int cc = col + e;
                    float v = acc[mi][ni][2*half + e];
                    if (bias)  v += bias[cc];
                    if (bbias) v += bbias[(size_t)(rr/npb)*N + cc];
                    if (bng) {
                        float sc = rsqrtf(bnv[cc] + 1e-5f);
                        v = (v - bnm[cc]) * sc * bng[cc] + bnb[cc];
                    }
                    if (relu) v = fmaxf(v, 0.f);
                    vv[e] = v;
                    if (maxpart) atomMaxF(&smax[cc - n0], v);
                }
                if (Ch) {
                    uint32_t lo;
                    uint32_t hi = packsplit(vv[0], vv[1], lo);
                    Ch[(size_t)rr*pitch2 + (col>>1)] = hi;
                    Cl[(size_t)rr*pitch2 + (col>>1)] = lo;
                }
            }
        }
    }
    if (maxpart) {
        __syncthreads();
        if (tid < 128) maxpart[(size_t)blockIdx.y*N + n0 + tid] = smax[tid];
    }
}

// ----------------------------- column max final -------------------------------
__global__ void colmax_final(const float* __restrict__ part, int nchunks, int nch,
                             float* __restrict__ out) {
    int gid = blockIdx.x*256 + threadIdx.x;
    if (gid >= BATCH*nch) return;
    int b = gid / nch, c = gid % nch;
    float mx = -3.4e38f;
    for (int ch = 0; ch < nchunks; ch++)
        mx = fmaxf(mx, part[((size_t)b*nchunks + ch)*nch + c]);
    out[gid] = mx;
}

// ----------------------------- warp GEMV (16 batches, float4) -----------------
__global__ void gemv16_kernel(const float* __restrict__ Z, int ldz,
                              const float* __restrict__ W, int ldw,
                              int N, int K,
                              const float* __restrict__ bias, int relu,
                              float* __restrict__ out) {
    int warp = (blockIdx.x*blockDim.x + threadIdx.x) >> 5;
    int lane = threadIdx.x & 31;
    if (warp >= N) return;
    float acc[BATCH];
    #pragma unroll
    for (int b = 0; b < BATCH; b++) acc[b] = 0.f;
    const float4* wr4 = (const float4*)(W + (size_t)warp*ldw);
    int K4 = K >> 2;
    for (int i = lane; i < K4; i += 32) {
        float4 w = wr4[i];
        #pragma unroll
        for (int b = 0; b < BATCH; b++) {
            float4 z = *(const float4*)&Z[(size_t)b*ldz + i*4];
            acc[b] += z.x*w.x + z.y*w.y + z.z*w.z + z.w*w.w;
        }
    }
    #pragma unroll
    for (int off = 16; off > 0; off >>= 1)
        #pragma unroll
        for (int b = 0; b < BATCH; b++)
            acc[b] += __shfl_down_sync(0xffffffffu, acc[b], off);
    if (lane == 0) {
        float bv = bias ? bias[warp] : 0.f;
        #pragma unroll
        for (int b = 0; b < BATCH; b++) {
            float v = acc[b] + bv;
            if (relu) v = fmaxf(v, 0.f);
            out[(size_t)b*N + warp] = v;
        }
    }
}

// ----------------------------- chamfer (smem-staged B, float4 quads) ----------
__global__ void chamfer_min_kernel(const float* __restrict__ A, int na,
                                   const float* __restrict__ Bp, int nb_,
                                   float* __restrict__ part) {
    __shared__ float sb[2432*3];
    __shared__ float red[256];
    int chunks = gridDim.x / BATCH;
    int b = blockIdx.x / chunks, ch = blockIdx.x % chunks;
    int t = threadIdx.x;
    const float* bp = Bp + (size_t)b*nb_*3;
    for (int i = t; i < nb_*3; i += 256) sb[i] = bp[i];
    __syncthreads();
    int i = ch*256 + t;
    float s = 0.f;
    if (i < na) {
        const float* ap = A + ((size_t)b*na + i)*3;
        float ax = ap[0], ay = ap[1], az = ap[2];
        const float4* sv4 = (const float4*)sb;
        float mn = 3.0e38f;
        int nq = nb_ >> 2;
        for (int j = 0; j < nq; j++) {
            float4 q0 = sv4[j*3+0];
            float4 q1 = sv4[j*3+1];
            float4 q2 = sv4[j*3+2];
            float dx, dy, dz, d;
            dx = q0.x-ax; dy = q0.y-ay; dz = q0.z-az;
            d = dx*dx + dy*dy + dz*dz; mn = fminf(mn, d);
            dx = q0.w-ax; dy = q1.x-ay; dz = q1.y-az;
            d = dx*dx + dy*dy + dz*dz; mn = fminf(mn, d);
            dx = q1.z-ax; dy = q1.w-ay; dz = q2.x-az;
            d = dx*dx + dy*dy + dz*dz; mn = fminf(mn, d);
            dx = q2.y-ax; dy = q2.z-ay; dz = q2.w-az;
            d = dx*dx + dy*dy + dz*dz; mn = fminf(mn, d);
        }
        s = sqrtf(fmaxf(mn, 1e-12f));
    }
    red[t] = s;
    __syncthreads();
    for (int r = 128; r > 0; r >>= 1) {
        if (t < r) red[t] += red[t+r];
        __syncthreads();
    }
    if (t == 0) part[blockIdx.x] = red[0];
}
__global__ void chamfer_final_kernel(const float* __restrict__ p1, int n1,
                                     const float* __restrict__ p2, int n2,
                                     float w, int tot1, int tot2,
                                     float* __restrict__ slot) {
    double s1 = 0.0, s2 = 0.0;
    for (int i = 0; i < n1; i++) s1 += p1[i];
    for (int i = 0; i < n2; i++) s2 += p2[i];
    *slot = w * 0.5f * (float)(s1/tot1 + s2/tot2);
}

// ----------------------------- huber latent loss ------------------------------
__global__ void huber_kernel(const float* __restrict__ f1, const float* __restrict__ f2,
                             int n, float w, float* __restrict__ slot) {
    int t = threadIdx.x;
    float s = 0.f;
    for (int i = t; i < n; i += 256) {
        float d = f1[i] - f2[i];
        float ad = fabsf(d);
        s += (ad < 1.f) ? 0.5f*d*d : (ad - 0.5f);
    }
    __shared__ float red[256];
    red[t] = s;
    __syncthreads();
    for (int r = 128; r > 0; r >>= 1) {
        if (t < r) red[t] += red[t+r];
        __syncthreads();
    }
    if (t == 0) *slot = w * red[0] / n;
}

// ----------------------------- normals ----------------------------------------
__device__ void eig3_min(double a00, double a01, double a02,
                         double a11, double a12, double a22,
                         double* vx, double* vy, double* vz) {
    double p1 = a01*a01 + a02*a02 + a12*a12;
    double ex = 1, ey = 0, ez = 0;
    if (p1 < 1e-300) {
        if (a00 <= a11 && a00 <= a22) { ex=1; ey=0; ez=0; }
        else if (a11 <= a22)          { ex=0; ey=1; ez=0; }
        else                          { ex=0; ey=0; ez=1; }
    } else {
        double q  = (a00 + a11 + a22) / 3.0;
        double b00 = a00-q, b11 = a11-q, b22 = a22-q;
        double p2 = b00*b00 + b11*b11 + b22*b22 + 2.0*p1;
        double p  = sqrt(p2/6.0);
        double inv = 1.0/p;
        double c00 = b00*inv, c01 = a01*inv, c02 = a02*inv;
        double c11 = b11*inv, c12 = a12*inv, c22 = b22*inv;
        double detB = c00*(c11*c22 - c12*c12) - c01*(c01*c22 - c12*c02) + c02*(c01*c12 - c11*c02);
        double r = detB * 0.5;
        r = fmin(1.0, fmax(-1.0, r));
        double phi = acos(r) / 3.0;
        double l1 = q + 2.0*p*cos(phi);
        double l3 = q + 2.0*p*cos(phi + 2.0943951023931953);
        double l2 = 3.0*q - l1 - l3;
        double A1[3][3] = {{a00-l1, a01, a02}, {a01, a11-l1, a12}, {a02, a12, a22-l1}};
        double A2[3][3] = {{a00-l2, a01, a02}, {a01, a11-l2, a12}, {a02, a12, a22-l2}};
        double Mby[3][3];
        for (int i = 0; i < 3; i++)
            for (int j = 0; j < 3; j++)
                Mby[i][j] = A1[i][0]*A2[0][j] + A1[i][1]*A2[1][j] + A1[i][2]*A2[2][j];
        double bestn = -1.0;
        for (int j = 0; j < 3; j++) {
            double nx = Mby[0][j], ny = Mby[1][j], nz = Mby[2][j];
            double nn = nx*nx + ny*ny + nz*nz;
            if (nn > bestn) { bestn = nn; ex = nx; ey = ny; ez = nz; }
        }
        if (bestn < 1e-200) {
            double C[3][3] = {{a00-l3, a01, a02}, {a01, a11-l3, a12}, {a02, a12, a22-l3}};
            bestn = -1.0;
            int pairs[3][2] = {{0,1},{0,2},{1,2}};
            for (int pp = 0; pp < 3; pp++) {
                int r0 = pairs[pp][0], r1 = pairs[pp][1];
                double nx = C[r0][1]*C[r1][2] - C[r0][2]*C[r1][1];
                double ny = C[r0][2]*C[r1][0] - C[r0][0]*C[r1][2];
                double nz = C[r0][0]*C[r1][1] - C[r0][1]*C[r1][0];
                double nn = nx*nx + ny*ny + nz*nz;
                if (nn > bestn) { bestn = nn; ex = nx; ey = ny; ez = nz; }
            }
            if (bestn < 1e-200) { ex = 1; ey = 0; ez = 0; }
        }
    }
    double nrm = sqrt(ex*ex + ey*ey + ez*ez);
    double invn = 1.0 / nrm;
    *vx = ex*invn; *vy = ey*invn; *vz = ez*invn;
}

__global__ void normals_kernel(const float* __restrict__ pred,
                               const int* __restrict__ idx,
                               float* __restrict__ nrm) {
    int gid = blockIdx.x*256 + threadIdx.x;
    if (gid >= BATCH*NPTS) return;
    int b = gid / NPTS;
    const int* ip = idx + (size_t)gid*NBH;
    const float* base = pred + (size_t)b*NPTS*3;
    float px[NBH], py[NBH], pz[NBH];
    float sx = 0.f, sy = 0.f, sz = 0.f;
    #pragma unroll 4
    for (int k = 0; k < NBH; k++) {
        const float* p = base + (size_t)ip[k]*3;
        px[k] = p[0]; py[k] = p[1]; pz[k] = p[2];
        sx += px[k]; sy += py[k]; sz += pz[k];
    }
    float mx = sx*(1.f/NBH), my = sy*(1.f/NBH), mz = sz*(1.f/NBH);
    float cxx=0.f, cxy=0.f, cxz=0.f, cyy=0.f, cyz=0.f, czz=0.f;
    #pragma unroll 4
    for (int k = 0; k < NBH; k++) {
        float dx = px[k]-mx, dy = py[k]-my, dz = pz[k]-mz;
        cxx += dx*dx; cxy += dx*dy; cxz += dx*dz;
        cyy += dy*dy; cyz += dy*dz; czz += dz*dz;
    }
    float inv = 1.f/NBH;
    double vx, vy, vz;
    eig3_min((double)(cxx*inv), (double)(cxy*inv), (double)(cxz*inv),
             (double)(cyy*inv), (double)(cyz*inv), (double)(czz*inv),
             &vx, &vy, &vz);
    const float* xp = pred + (size_t)gid*3;
    double proj = 0.0;
    #pragma unroll 4
    for (int k = 0; k < NBH; k++)
        proj += (px[k]-xp[0])*vx + (py[k]-xp[1])*vy + (pz[k]-xp[2])*vz;
    double sgn = (proj >= 0.0) ? 1.0 : -1.0;
    nrm[(size_t)gid*3+0] = (float)(vx*sgn);
    nrm[(size_t)gid*3+1] = (float)(vy*sgn);
    nrm[(size_t)gid*3+2] = (float)(vz*sgn);
}

__global__ void manifold_kernel(const float* __restrict__ nrm,
                                const int* __restrict__ idx,
                                float* __restrict__ outstd) {
    int gid = blockIdx.x*256 + threadIdx.x;
    if (gid >= BATCH*NPTS) return;
    int b = gid / NPTS;
    const int* ip = idx + (size_t)gid*NBH;
    const float* base = nrm + (size_t)b*NPTS*3;
    const float* a = base + (size_t)ip[0]*3;
    float ax = a[0], ay = a[1], az = a[2];
    float an = fmaxf(sqrtf(ax*ax + ay*ay + az*az), 1e-6f);
    float vals[SUP];
    #pragma unroll
    for (int j = 0; j < SUP; j++) {
        const float* nj = base + (size_t)ip[j]*3;
        float nn = fmaxf(sqrtf(nj[0]*nj[0] + nj[1]*nj[1] + nj[2]*nj[2]), 1e-6f);
        float cosv = (ax*nj[0] + ay*nj[1] + az*nj[2]) / (an * nn);
        vals[j] = 1.f - cosv;
    }
    float mean = 0.f;
    #pragma unroll
    for (int j = 0; j < SUP; j++) mean += vals[j];
    mean /= SUP;
    float var = 0.f;
    #pragma unroll
    for (int j = 0; j < SUP; j++) { float d = vals[j]-mean; var += d*d; }
    var /= (SUP - 1);
    outstd[gid] = sqrtf(fmaxf(var, 0.f));
}

__global__ void mean_kernel(const float* __restrict__ in, int n, float w,
                            float* __restrict__ slot) {
    int t = threadIdx.x;
    float s = 0.f;
    for (int i = t; i < n; i += 256) s += in[i];
    __shared__ float red[256];
    red[t] = s;
    __syncthreads();
    for (int r = 128; r > 0; r >>= 1) {
        if (t < r) red[t] += red[t+r];
        __syncthreads();
    }
    if (t == 0) *slot = w * red[0] / n;
}

__global__ void final_kernel(const float* __restrict__ loss, float* __restrict__ out) {
    out[0] = loss[0] + loss[1] + loss[2] + loss[3];
    out[1] = loss[0];
    out[2] = loss[1];
    out[3] = loss[2];
    out[4] = loss[3];
}

// ----------------------------- host-side orchestration -----------------------
static void* sym(const void* symbol) {
    void* p = nullptr;
    cudaGetSymbolAddress(&p, symbol);
    return p;
}

struct Params {
    const float *W1,*b1,*g1,*be1,*m1,*v1,*W2,*b2,*W3,*b3,*g2,*be2,*m2,*v2,*W4,*b4;
    const float *D1W,*D1b,*D2W,*D2b,*D3W,*D3b,*D4W,*D4b;
};

#define GEMM_SMEM (3*GSTG*4)

static void run_encoder(const float* x, int npts, float* feat_out, const Params& P,
                        float* gmax, float* gb, float* cmpart, cudaStream_t st) {
    int M = BATCH * npts;
    int nchunks = npts / 256;
    uint32_t* h1h = (uint32_t*)sym(g_h1h); uint32_t* h1l = (uint32_t*)sym(g_h1l);
    uint32_t* h2h = (uint32_t*)sym(g_h2h); uint32_t* h2l = (uint32_t*)sym(g_h2l);
    uint32_t* h4h = (uint32_t*)sym(g_h4h); uint32_t* h4l = (uint32_t*)sym(g_h4l);
    uint32_t* w2h = (uint32_t*)sym(g_w2h); uint32_t* w2l = (uint32_t*)sym(g_w2l);
    uint32_t* w3h = (uint32_t*)sym(g_w3h); uint32_t* w3l = (uint32_t*)sym(g_w3l);
    uint32_t* w4h = (uint32_t*)sym(g_w4h); uint32_t* w4l = (uint32_t*)sym(g_w4l);

    layer1_kernel<<<(M*64 + 255)/256, 256, 0, st>>>(x, P.W1, P.b1, P.g1, P.be1, P.m1, P.v1,
                                                    h1h, h1l, M);
    {
        dim3 grid(256/128, M/256);
        gemm_tc<<<grid, 512, GEMM_SMEM, st>>>(h1h, h1l, 64, w2h, w2l, 64, M, 256, 128,
                               P.b2, nullptr, 1, nullptr, nullptr, nullptr, nullptr, 0,
                               h2h, h2l, cmpart);
    }
    colmax_final<<<(BATCH*256 + 255)/256, 256, 0, st>>>(cmpart, nchunks, 256, gmax);
    gemv16_kernel<<<(512 + 7)/8, 256, 0, st>>>(gmax, 256, P.W3, 512, 512, 256, P.b3, 0, gb);
    {
        dim3 grid(512/128, M/256);
        gemm_tc<<<grid, 512, GEMM_SMEM, st>>>(h2h, h2l, 128, w3h, w3l, 128, M, 512, 256,
                               nullptr, gb, npts, P.g2, P.be2, P.m2, P.v2, 1,
                               h4h, h4l, nullptr);
    }
    {
        dim3 grid(1024/128, M/256);
        gemm_tc<<<grid, 512, GEMM_SMEM, st>>>(h4h, h4l, 256, w4h, w4l, 256, M, 1024, 512,
                               P.b4, nullptr, 1, nullptr, nullptr, nullptr, nullptr, 0,
                               nullptr, nullptr, cmpart);
    }
    colmax_final<<<(BATCH*1024 + 255)/256, 256, 0, st>>>(cmpart, nchunks, 1024, feat_out);
}

extern "C" void kernel_launch(void* const* d_in, const int* in_sizes, int n_in,
                              void* d_out, int out_size) {
    const float* pts = (const float*)d_in[0];
    Params P;
    P.W1  = (const float*)d_in[1];  P.b1  = (const float*)d_in[2];
    P.g1  = (const float*)d_in[3];  P.be1 = (const float*)d_in[4];
    P.m1  = (const float*)d_in[5];  P.v1  = (const float*)d_in[6];
    P.W2  = (const float*)d_in[7];  P.b2  = (const float*)d_in[8];
    P.W3  = (const float*)d_in[9];  P.b3  = (const float*)d_in[10];
    P.g2  = (const float*)d_in[11]; P.be2 = (const float*)d_in[12];
    P.m2  = (const float*)d_in[13]; P.v2  = (const float*)d_in[14];
    P.W4  = (const float*)d_in[15]; P.b4  = (const float*)d_in[16];
    P.D1W = (const float*)d_in[17]; P.D1b = (const float*)d_in[18];
    P.D2W = (const float*)d_in[19]; P.D2b = (const float*)d_in[20];
    P.D3W = (const float*)d_in[21]; P.D3b = (const float*)d_in[22];
    P.D4W = (const float*)d_in[23]; P.D4b = (const float*)d_in[24];
    float* out = (float*)d_out;

    static cudaStream_t s1 = nullptr, s2 = nullptr, s3 = nullptr;
    static cudaEvent_t evStart = nullptr, evSplit = nullptr, evPred = nullptr;
    static cudaEvent_t evA = nullptr, evB = nullptr, evD = nullptr;
    if (!s1) {
        cudaStreamCreateWithFlags(&s1, cudaStreamNonBlocking);
        cudaStreamCreateWithFlags(&s2, cudaStreamNonBlocking);
        cudaStreamCreateWithFlags(&s3, cudaStreamNonBlocking);
        cudaEventCreateWithFlags(&evStart, cudaEventDisableTiming);
        cudaEventCreateWithFlags(&evSplit, cudaEventDisableTiming);
        cudaEventCreateWithFlags(&evPred,  cudaEventDisableTiming);
        cudaEventCreateWithFlags(&evA, cudaEventDisableTiming);
        cudaEventCreateWithFlags(&evB, cudaEventDisableTiming);
        cudaEventCreateWithFlags(&evD, cudaEventDisableTiming);
        cudaFuncSetAttribute(gemm_tc, cudaFuncAttributeMaxDynamicSharedMemorySize, GEMM_SMEM);
    }

    int*   fps    = (int*)  sym(g_fps);
    float* center = (float*)sym(g_center);
    int*   knnc   = (int*)  sym(g_knnc);
    float* reb0   = (float*)sym(g_reb0);
    float* reb1   = (float*)sym(g_reb1);
    float* encin2 = (float*)sym(g_encin2);
    float* gmax   = (float*)sym(g_gmax);
    float* gb     = (float*)sym(g_gb);
    float* cmpart = (float*)sym(g_cmpart);
    float* feat   = (float*)sym(g_feat);
    float* feat2  = (float*)sym(g_feat2);
    float* dec1   = (float*)sym(g_dec1);
    float* dec2   = (float*)sym(g_dec2);
    float* dec3   = (float*)sym(g_dec3);
    float* pred   = (float*)sym(g_pred);
    int*   knngA  = (int*)  sym(g_knngA);
    int*   knngB  = (int*)  sym(g_knngB);
    int*   knngC  = (int*)  sym(g_knngC);
    float* gathA  = (float*)sym(g_gathA);
    float* gathB  = (float*)sym(g_gathB);
    int*   knnp   = (int*)  sym(g_knnp);
    float* nrm    = (float*)sym(g_normals);
    float* stdbuf = (float*)sym(g_std);
    float* partA1 = (float*)sym(g_partA1);
    float* partA2 = (float*)sym(g_partA2);
    float* partB1 = (float*)sym(g_partB1);
    float* partB2 = (float*)sym(g_partB2);
    float* loss   = (float*)sym(g_loss);

    // fork: weight splitting on s1, concurrent with FPS/grouping on main
    cudaEventRecord(evStart, 0);
    cudaStreamWaitEvent(s1, evStart, 0);
    splitw_kernel<<<(256*64 + 255)/256, 256, 0, s1>>>(P.W2, 128, 0, 256*64, 64,
                                               (uint32_t*)sym(g_w2h), (uint32_t*)sym(g_w2l));
    splitw_kernel<<<(512*128 + 255)/256, 256, 0, s1>>>(P.W3, 512, 256, 512*128, 128,
                                               (uint32_t*)sym(g_w3h), (uint32_t*)sym(g_w3l));
    splitw_kernel<<<(1024*256 + 255)/256, 256, 0, s1>>>(P.W4, 512, 0, 1024*256, 256,
                                               (uint32_t*)sym(g_w4h), (uint32_t*)sym(g_w4l));
    cudaEventRecord(evSplit, s1);

    // 1. FPS + center + grouping (main)
    fps_kernel<<<BATCH, 512>>>(pts, fps);
    gather3_kernel<<<(BATCH*NG + 255)/256, 256>>>(pts, NPTS, fps, NG, NG, center);
    knn_kernel<<<BATCH*NG, 256>>>(center, NG, NG, pts, NPTS, GS, knnc);
    gather3_kernel<<<(BATCH*2048 + 255)/256, 256>>>(pts, NPTS, knnc, NG*GS, 2048, reb0);
    gather3_kernel<<<(BATCH*1024 + 255)/256, 256>>>(pts, NPTS, knnc + O1*GS, NG*GS, 1024, reb1);

    // join splits before encoder GEMMs
    cudaStreamWaitEvent(0, evSplit, 0);

    // 2. encoder pass A + decoder (main)
    run_encoder(reb0, 2048, feat, P, gmax, gb, cmpart, 0);
    gemv16_kernel<<<2048/8, 256>>>(feat, 1024, P.D1W, 1024, 2048, 1024, P.D1b, 1, dec1);
    gemv16_kernel<<<2048/8, 256>>>(dec1, 2048, P.D2W, 2048, 2048, 2048, P.D2b, 1, dec2);
    gemv16_kernel<<<2048/8, 256>>>(dec2, 2048, P.D3W, 2048, 2048, 2048, P.D3b, 1, dec3);
    gemv16_kernel<<<6144/8, 256>>>(dec3, 2048, P.D4W, 2048, 6144, 2048, P.D4b, 0, pred);

    // fork after pred
    cudaEventRecord(evPred, 0);
    cudaStreamWaitEvent(s1, evPred, 0);
    cudaStreamWaitEvent(s2, evPred, 0);
    cudaStreamWaitEvent(s3, evPred, 0);

    // branch A (s1): l_recon
    knn_kernel<<<BATCH*64, 256, 0, s1>>>(center, NG, 64, pred, NPTS, NBRK, knngA);
    gather3_kernel<<<(BATCH*2432 + 255)/256, 256, 0, s1>>>(pred, NPTS, knngA, 64*NBRK, 2432, gathA);
    chamfer_min_kernel<<<BATCH*8, 256, 0, s1>>>(reb0, 2048, gathA, 2432, partA1);
    chamfer_min_kernel<<<BATCH*10, 256, 0, s1>>>(gathA, 2432, reb0, 2048, partA2);
    chamfer_final_kernel<<<1, 1, 0, s1>>>(partA1, BATCH*8, partA2, BATCH*10, 1.0f,
                                          BATCH*2048, BATCH*2432, loss + 0);
    cudaEventRecord(evA, s1);

    // branch B (s2): l_match
    knn_kernel<<<BATCH*32, 256, 0, s2>>>(center + O1*3, NG, 32, pred, NPTS, NBRK, knngB);
    gather3_kernel<<<(BATCH*1216 + 255)/256, 256, 0, s2>>>(pred, NPTS, knngB, 32*NBRK, 1216, gathB);
    chamfer_min_kernel<<<BATCH*4, 256, 0, s2>>>(reb1, 1024, gathB, 1216, partB1);
    chamfer_min_kernel<<<BATCH*5, 256, 0, s2>>>(gathB, 1216, reb1, 1024, partB2);
    chamfer_final_kernel<<<1, 1, 0, s2>>>(partB1, BATCH*4, partB2, BATCH*5, 1.0f,
                                          BATCH*1024, BATCH*1216, loss + 1);
    cudaEventRecord(evB, s2);

    // branch D (s3): l_man (heaviest independent chain)
    knn_kernel<<<BATCH*NPTS, 256, 0, s3>>>(pred, NPTS, NPTS, pred, NPTS, NBH, knnp);
    normals_kernel<<<(BATCH*NPTS + 255)/256, 256, 0, s3>>>(pred, knnp, nrm);
    manifold_kernel<<<(BATCH*NPTS + 255)/256, 256, 0, s3>>>(nrm, knnp, stdbuf);
    mean_kernel<<<1, 256, 0, s3>>>(stdbuf, BATCH*NPTS, 0.1f, loss + 3);
    cudaEventRecord(evD, s3);

    // branch C (main): l_latent encoder pass
    knn_kernel<<<BATCH*32, 256>>>(center + O2*3, NG, 32, pred, NPTS, GS, knngC);
    gather3_kernel<<<(BATCH*1024 + 255)/256, 256>>>(pred, NPTS, knngC, 32*GS, 1024, encin2);
    run_encoder(encin2, 1024, feat2, P, gmax, gb, cmpart, 0);
    huber_kernel<<<1, 256>>>(feat, feat2, BATCH*FEATD, 1.0f, loss + 2);

    // join all branches, then final
    cudaStreamWaitEvent(0, evA, 0);
    cudaStreamWaitEvent(0, evB, 0);
    cudaStreamWaitEvent(0, evD, 0);
    final_kernel<<<1, 1>>>(loss, out);
}

// round 14
// speedup vs baseline: 1.4044x; 1.0058x over previous
#include <cuda_runtime.h>
#include <cuda_bf16.h>
#include <math.h>
#include <stdint.h>

#define BATCH 16
#define NPTS 2048
#define NG 128
#define GS 32
#define O1 64
#define O2 96
#define FEATD 1024
#define NBRK 38
#define SUP 8
#define NBH 32

// ----------------------------- scratch (static device globals) ---------------
__device__ int   g_fps[BATCH*NG];
__device__ float g_center[BATCH*NG*3];
__device__ int   g_knnc[BATCH*NG*GS];
__device__ __align__(16) float g_reb0[BATCH*2048*3];
__device__ __align__(16) float g_reb1[BATCH*1024*3];
__device__ __align__(16) float g_encin2[BATCH*1024*3];
__device__ __align__(16) float g_gmax[BATCH*256];
__device__ __align__(16) float g_gb[BATCH*512];
__device__ float g_cmpart[256*1024];
__device__ __align__(16) float g_feat[BATCH*1024];
__device__ __align__(16) float g_feat2[BATCH*1024];
__device__ __align__(16) float g_dec1[BATCH*2048];
__device__ __align__(16) float g_dec2[BATCH*2048];
__device__ __align__(16) float g_dec3[BATCH*2048];
__device__ __align__(16) float g_pred[BATCH*2048*3];
__device__ int   g_knngA[BATCH*64*38];
__device__ int   g_knngB[BATCH*32*38];
__device__ int   g_knngC[BATCH*32*32];
__device__ __align__(16) float g_gathA[BATCH*2432*3];
__device__ __align__(16) float g_gathB[BATCH*1216*3];
__device__ int   g_knnp[BATCH*2048*32];
__device__ float g_normals[BATCH*2048*3];
__device__ float g_std[BATCH*2048];
__device__ float g_partA1[128];
__device__ float g_partA2[160];
__device__ float g_partB1[64];
__device__ float g_partB2[80];
__device__ float g_loss[4];

// split (bf16 hi/lo packed pairs) buffers
__device__ __align__(16) uint32_t g_w2h[256*64],    g_w2l[256*64];
__device__ __align__(16) uint32_t g_w3h[512*128],   g_w3l[512*128];
__device__ __align__(16) uint32_t g_w4h[1024*256],  g_w4l[1024*256];
__device__ __align__(16) uint32_t g_h1h[BATCH*2048*64],  g_h1l[BATCH*2048*64];
__device__ __align__(16) uint32_t g_h2h[BATCH*2048*128], g_h2l[BATCH*2048*128];
__device__ __align__(16) uint32_t g_h4h[BATCH*2048*256], g_h4l[BATCH*2048*256];

// ----------------------------- helpers ---------------------------------------
__device__ __forceinline__ uint32_t packsplit(float a, float b, uint32_t& lo) {
    __nv_bfloat16 ha = __float2bfloat16_rn(a);
    __nv_bfloat16 hb = __float2bfloat16_rn(b);
    __nv_bfloat16 la = __float2bfloat16_rn(a - __bfloat162float(ha));
    __nv_bfloat16 lb = __float2bfloat16_rn(b - __bfloat162float(hb));
    __nv_bfloat162 l2 = __halves2bfloat162(la, lb);
    __nv_bfloat162 h2 = __halves2bfloat162(ha, hb);
    lo = *(uint32_t*)&l2;
    return *(uint32_t*)&h2;
}
__device__ __forceinline__ void mma_bf16(float* d, const uint32_t* a, const uint32_t* b) {
    asm volatile("mma.sync.aligned.m16n8k16.row.col.f32.bf16.bf16.f32 "
        "{%0,%1,%2,%3}, {%4,%5,%6,%7}, {%8,%9}, {%0,%1,%2,%3};"
        : "+f"(d[0]), "+f"(d[1]), "+f"(d[2]), "+f"(d[3])
        : "r"(a[0]), "r"(a[1]), "r"(a[2]), "r"(a[3]), "r"(b[0]), "r"(b[1]));
}
__device__ __forceinline__ void atomMaxF(float* a, float v) {
    if (v >= 0.f) atomicMax((int*)a, __float_as_int(v));
    else atomicMin((unsigned int*)a, __float_as_uint(v));
}
__device__ __forceinline__ uint32_t s2a(const void* p) {
    return (uint32_t)__cvta_generic_to_shared(p);
}
__device__ __forceinline__ void cpasync16(uint32_t saddr, const void* g) {
    asm volatile("cp.async.cg.shared.global [%0], [%1], 16;" :: "r"(saddr), "l"(g));
}

// ----------------------------- FPS (512 thr, 1 barrier/round) -----------------
__global__ void fps_kernel(const float* __restrict__ pts, int* __restrict__ out) {
    __shared__ float sx[NPTS], sy[NPTS], sz[NPTS];
    __shared__ unsigned long long slot[NG];
    int b = blockIdx.x, t = threadIdx.x, lane = t & 31;
    const float* p = pts + (size_t)b*NPTS*3;
    for (int i = t; i < NPTS; i += 512) {
        sx[i] = p[3*i]; sy[i] = p[3*i+1]; sz[i] = p[3*i+2];
    }
    for (int i = t; i < NG; i += 512) slot[i] = 0ULL;
    float px[4], py[4], pz[4], dv[4];
    #pragma unroll
    for (int r = 0; r < 4; r++) {
        int i = t + r*512;
        px[r] = p[3*i]; py[r] = p[3*i+1]; pz[r] = p[3*i+2];
        dv[r] = 1e10f;
    }
    __syncthreads();
    int far = 0;
    for (int g = 0; g < NG; g++) {
        if (t == 0) out[b*NG + g] = far;
        float cx = sx[far], cy = sy[far], cz = sz[far];
        float bv = 0.f; int bi = 0;
        #pragma unroll
        for (int r = 0; r < 4; r++) {
            float dx = px[r]-cx, dy = py[r]-cy, dz = pz[r]-cz;
            float d = dx*dx + dy*dy + dz*dz;
            float m = fminf(dv[r], d);
            dv[r] = m;
            if (r == 0) { bv = m; bi = t; }
            else if (m > bv) { bv = m; bi = t + r*512; }
        }
        #pragma unroll
        for (int off = 16; off > 0; off >>= 1) {
            float ov = __shfl_down_sync(0xffffffffu, bv, off);
            int   oi = __shfl_down_sync(0xffffffffu, bi, off);
            if (ov > bv || (ov == bv && oi < bi)) { bv = ov; bi = oi; }
        }
        if (lane == 0) {
            unsigned long long key =
                ((unsigned long long)__float_as_uint(bv) << 32) |
                (unsigned long long)(unsigned)(~bi);
            atomicMax(&slot[g], key);
        }
        __syncthreads();
        far = (int)(~(unsigned)(slot[g] & 0xffffffffu));
    }
}

// ----------------------------- gather ----------------------------------------
__global__ void gather3_kernel(const float* __restrict__ db, int dbstride,
                               const int* __restrict__ idx, int idxstride,
                               int cnt, float* __restrict__ out) {
    int gid = blockIdx.x*blockDim.x + threadIdx.x;
    if (gid >= BATCH*cnt) return;
    int b = gid / cnt, i = gid % cnt;
    int j = idx[b*idxstride + i];
    const float* s = db + ((size_t)b*dbstride + j)*3;
    float* o = out + (size_t)gid*3;
    o[0] = s[0]; o[1] = s[1]; o[2] = s[2];
}

// ----------------------------- kNN (register-cached incremental, round-5) -----
__global__ void knn_kernel(const float* __restrict__ q, int qstride, int nq,
                           const float* __restrict__ db, int dbstride,
                           int k, int* __restrict__ out) {
    __shared__ float swv[8];
    __shared__ int   swi[8];
    __shared__ int   swin;
    int b = blockIdx.x / nq, qi = blockIdx.x % nq;
    int t = threadIdx.x, lane = t & 31, wid = t >> 5;
    const float* qp = q + ((size_t)b*qstride + qi)*3;
    float qx = qp[0], qy = qp[1], qz = qp[2];
    const float* dp = db + (size_t)b*dbstride*3;
    float dv[8];
    #pragma unroll
    for (int r = 0; r < 8; r++) {
        int i = t + r*256;
        float dx = dp[3*i]-qx, dy = dp[3*i+1]-qy, dz = dp[3*i+2]-qz;
        dv[r] = dx*dx + dy*dy + dz*dz;
    }
    float lmv = 3.9e38f; int lmi = (1<<30);
    #pragma unroll
    for (int r = 0; r < 8; r++)
        if (dv[r] < lmv) { lmv = dv[r]; lmi = t + r*256; }
    {
        float rv = lmv; int ri = lmi;
        #pragma unroll
        for (int off = 16; off > 0; off >>= 1) {
            float ov = __shfl_down_sync(0xffffffffu, rv, off);
            int   oi = __shfl_down_sync(0xffffffffu, ri, off);
            if (ov < rv || (ov == rv && oi < ri)) { rv = ov; ri = oi; }
        }
        if (lane == 0) { swv[wid] = rv; swi[wid] = ri; }
    }
    __syncthreads();
    int* op = out + ((size_t)b*nq + qi)*k;
    for (int s = 0; s < k; s++) {
        if (wid == 0) {
            float rv = (lane < 8) ? swv[lane] : 3.9e38f;
            int   ri = (lane < 8) ? swi[lane] : (1<<30);
            #pragma unroll
            for (int off = 4; off > 0; off >>= 1) {
                float ov = __shfl_down_sync(0xffffffffu, rv, off);
                int   oi = __shfl_down_sync(0xffffffffu, ri, off);
                if (ov < rv || (ov == rv && oi < ri)) { rv = ov; ri = oi; }
            }
            if (lane == 0) { op[s] = ri; swin = ri; }
        }
        __syncthreads();
        int win = swin;
        int owner = win & 255;
        if (t == owner) {
            int r0 = win >> 8;
            #pragma unroll
            for (int r = 0; r < 8; r++) if (r == r0) dv[r] = 3.9e38f;
            lmv = 3.9e38f; lmi = (1<<30);
            #pragma unroll
            for (int r = 0; r < 8; r++)
                if (dv[r] < lmv) { lmv = dv[r]; lmi = t + r*256; }
        }
        if ((t >> 5) == (owner >> 5)) {
            float rv = lmv; int ri = lmi;
            #pragma unroll
            for (int off = 16; off > 0; off >>= 1) {
                float ov = __shfl_down_sync(0xffffffffu, rv, off);
                int   oi = __shfl_down_sync(0xffffffffu, ri, off);
                if (ov < rv || (ov == rv && oi < ri)) { rv = ov; ri = oi; }
            }
            if (lane == 0) { swv[wid] = rv; swi[wid] = ri; }
        }
        __syncthreads();
    }
}

// ----------------------------- weight splitting -------------------------------
__global__ void splitw_kernel(const float* __restrict__ W, int ld, int coloff,
                              int total, int cols2,
                              uint32_t* __restrict__ Oh, uint32_t* __restrict__ Ol) {
    int gid = blockIdx.x*256 + threadIdx.x;
    if (gid >= total) return;
    int n = gid / cols2, j = gid % cols2;
    float a = W[(size_t)n*ld + coloff + 2*j];
    float b = W[(size_t)n*ld + coloff + 2*j + 1];
    uint32_t lo;
    uint32_t hi = packsplit(a, b, lo);
    Oh[gid] = hi; Ol[gid] = lo;
}

// ----------------------------- encoder layer 1 (K=3), split output ------------
__global__ void layer1_kernel(const float* __restrict__ x,
                              const float* __restrict__ W1, const float* __restrict__ b1,
                              const float* __restrict__ g1, const float* __restrict__ be1,
                              const float* __restrict__ m1, const float* __restrict__ v1,
                              uint32_t* __restrict__ h1h, uint32_t* __restrict__ h1l,
                              int M) {
    int gid = blockIdx.x*256 + threadIdx.x;
    if (gid >= M*64) return;
    int m = gid >> 6, j = gid & 63;
    const float* xp = x + (size_t)m*3;
    float x0 = xp[0], x1 = xp[1], x2 = xp[2];
    float v[2];
    #pragma unroll
    for (int h = 0; h < 2; h++) {
        int n = 2*j + h;
        float acc = x0*W1[n*3] + x1*W1[n*3+1] + x2*W1[n*3+2] + b1[n];
        float sc = rsqrtf(v1[n] + 1e-5f);
        float val = (acc - m1[n]) * sc * g1[n] + be1[n];
        v[h] = fmaxf(val, 0.f);
    }
    uint32_t lo;
    uint32_t hi = packsplit(v[0], v[1], lo);
    h1h[gid] = hi; h1l[gid] = lo;
}

// ----------------------------- tensor-core GEMM (3x bf16 split, cp.async) -----
#define GSTG 15360         // u32 per stage
#define GOFF_AL 5120
#define GOFF_WH 10240
#define GOFF_WL 12800

__device__ __forceinline__ void gemm_issue(uint32_t* stg,
        const uint32_t* Ah, const uint32_t* Al, int lda2,
        const uint32_t* Wh, const uint32_t* Wl, int ldw2,
        int m0, int n0, int k2, int tid) {
    #pragma unroll
    for (int p = 0; p < 2; p++) {
        int idx = tid + p*512;
        int r = idx >> 2, sl = idx & 3;
        size_t go = (size_t)(m0 + r)*lda2 + k2 + sl*4;
        cpasync16(s2a(stg + r*20 + sl*4), Ah + go);
        cpasync16(s2a(stg + GOFF_AL + r*20 + sl*4), Al + go);
    }
    {
        int idx = tid;
        int r = idx >> 2, sl = idx & 3;
        size_t go = (size_t)(n0 + r)*ldw2 + k2 + sl*4;
        cpasync16(s2a(stg + GOFF_WH + r*20 + sl*4), Wh + go);
        cpasync16(s2a(stg + GOFF_WL + r*20 + sl*4), Wl + go);
    }
    asm volatile("cp.async.commit_group;" ::: "memory");
}

__global__ __launch_bounds__(512, 1) void gemm_tc(
        const uint32_t* __restrict__ Ah, const uint32_t* __restrict__ Al, int lda2,
        const uint32_t* __restrict__ Wh, const uint32_t* __restrict__ Wl, int ldw2,
        int M, int N, int K,
        const float* __restrict__ bias,
        const float* __restrict__ bbias, int npb,
        const float* __restrict__ bng, const float* __restrict__ bnb,
        const float* __restrict__ bnm, const float* __restrict__ bnv,
        int relu,
        uint32_t* __restrict__ Ch, uint32_t* __restrict__ Cl,
        float* __restrict__ maxpart) {
    extern __shared__ uint32_t dsm[];
    __shared__ float smax[128];
    int tid = threadIdx.x;
    int warp = tid >> 5, lane = tid & 31;
    int wm = (warp >> 2) * 64, wn = (warp & 3) * 32;
    int m0 = blockIdx.y * 256, n0 = blockIdx.x * 128;
    int g = lane >> 2, tg = lane & 3;

    if (maxpart && tid < 128) smax[tid] = -3.4e38f;

    float acc[4][4][4];
    #pragma unroll
    for (int mi = 0; mi < 4; mi++)
        #pragma unroll
        for (int ni = 0; ni < 4; ni++)
            #pragma unroll
            for (int r = 0; r < 4; r++) acc[mi][ni][r] = 0.f;

    int nch = K / 32;
    gemm_issue(dsm, Ah, Al, lda2, Wh, Wl, ldw2, m0, n0, 0, tid);
    if (nch > 1) gemm_issue(dsm + GSTG, Ah, Al, lda2, Wh, Wl, ldw2, m0, n0, 16, tid);

    for (int c = 0; c < nch; c++) {
        if (c < nch - 1) asm volatile("cp.async.wait_group 1;" ::: "memory");
        else             asm volatile("cp.async.wait_group 0;" ::: "memory");
        __syncthreads();
        if (c + 2 < nch)
            gemm_issue(dsm + ((c+2)%3)*GSTG, Ah, Al, lda2, Wh, Wl, ldw2,
                       m0, n0, (c+2)*16, tid);
        const uint32_t* sA  = dsm + (c%3)*GSTG;
        const uint32_t* sAl = sA + GOFF_AL;
        const uint32_t* sW  = sA + GOFF_WH;
        const uint32_t* sWl = sA + GOFF_WL;

        #pragma unroll
        for (int ks = 0; ks < 2; ks++) {
            int kk = ks * 8;
            uint32_t ah[4][4], alr[4][4];
            #pragma unroll
            for (int mi = 0; mi < 4; mi++) {
                int r0 = wm + mi*16 + g;
                ah[mi][0]  = sA [r0*20     + kk+tg];
                ah[mi][1]  = sA [(r0+8)*20 + kk+tg];
                ah[mi][2]  = sA [r0*20     + kk+4+tg];
                ah[mi][3]  = sA [(r0+8)*20 + kk+4+tg];
                alr[mi][0] = sAl[r0*20     + kk+tg];
                alr[mi][1] = sAl[(r0+8)*20 + kk+tg];
                alr[mi][2] = sAl[r0*20     + kk+4+tg];
                alr[mi][3] = sAl[(r0+8)*20 + kk+4+tg];
            }
            #pragma unroll
            for (int nh = 0; nh < 2; nh++) {
                uint32_t bh[2][2], blr[2][2];
                #pragma unroll
                for (int nn = 0; nn < 2; nn++) {
                    int n = wn + (nh*2 + nn)*8 + g;
                    bh[nn][0]  = sW [n*20 + kk+tg];
                    bh[nn][1]  = sW [n*20 + kk+4+tg];
                    blr[nn][0] = sWl[n*20 + kk+tg];
                    blr[nn][1] = sWl[n*20 + kk+4+tg];
                }
                #pragma unroll
                for (int mi = 0; mi < 4; mi++)
                    #pragma unroll
                    for (int nn = 0; nn < 2; nn++) {
                        float* a = acc[mi][nh*2 + nn];
                        mma_bf16(a, ah[mi],  blr[nn]);
                        mma_bf16(a, alr[mi], bh[nn]);
                        mma_bf16(a, ah[mi],  bh[nn]);
                    }
            }
        }
    }

    // epilogue
    int pitch2 = N >> 1;
    #pragma unroll
    for (int mi = 0; mi < 4; mi++) {
        #pragma unroll
        for (int ni = 0; ni < 4; ni++) {
            int row = m0 + wm + mi*16 + g;
            int col = n0 + wn + ni*8 + 2*tg;
            #pragma unroll
            for (int half = 0; half < 2; half++) {
                int rr = row + half*8;
                float vv[2];
                #pragma unroll
                for (int e = 0; e < 2; e++) {
                    int cc = col + e;
                    float v = acc[mi][ni][2*half + e];
                    if (bias)  v += bias[cc];
                    if (bbias) v += bbias[(size_t)(rr/npb)*N + cc];
                    if (bng) {
                        float sc = rsqrtf(bnv[cc] + 1e-5f);
                        v = (v - bnm[cc]) * sc * bng[cc] + bnb[cc];
                    }
                    if (relu) v = fmaxf(v, 0.f);
                    vv[e] = v;
                    if (maxpart) atomMaxF(&smax[cc - n0], v);
                }
                if (Ch) {
                    uint32_t lo;
                    uint32_t hi = packsplit(vv[0], vv[1], lo);
                    Ch[(size_t)rr*pitch2 + (col>>1)] = hi;
                    Cl[(size_t)rr*pitch2 + (col>>1)] = lo;
                }
            }
        }
    }
    if (maxpart) {
        __syncthreads();
        if (tid < 128) maxpart[(size_t)blockIdx.y*N + n0 + tid] = smax[tid];
    }
}

// ----------------------------- column max final -------------------------------
__global__ void colmax_final(const float* __restrict__ part, int nchunks, int nch,
                             float* __restrict__ out) {
    int gid = blockIdx.x*256 + threadIdx.x;
    if (gid >= BATCH*nch) return;
    int b = gid / nch, c = gid % nch;
    float mx = -3.4e38f;
    for (int ch = 0; ch < nchunks; ch++)
        mx = fmaxf(mx, part[((size_t)b*nchunks + ch)*nch + c]);
    out[gid] = mx;
}

// ----------------------------- warp GEMV (16 batches, float4) -----------------
__global__ void gemv16_kernel(const float* __restrict__ Z, int ldz,
                              const float* __restrict__ W, int ldw,
                              int N, int K,
                              const float* __restrict__ bias, int relu,
                              float* __restrict__ out) {
    int warp = (blockIdx.x*blockDim.x + threadIdx.x) >> 5;
    int lane = threadIdx.x & 31;
    if (warp >= N) return;
    float acc[BATCH];
    #pragma unroll
    for (int b = 0; b < BATCH; b++) acc[b] = 0.f;
    const float4* wr4 = (const float4*)(W + (size_t)warp*ldw);
    int K4 = K >> 2;
    for (int i = lane; i < K4; i += 32) {
        float4 w = wr4[i];
        #pragma unroll
        for (int b = 0; b < BATCH; b++) {
            float4 z = *(const float4*)&Z[(size_t)b*ldz + i*4];
            acc[b] += z.x*w.x + z.y*w.y + z.z*w.z + z.w*w.w;
        }
    }
    #pragma unroll
    for (int off = 16; off > 0; off >>= 1)
        #pragma unroll
        for (int b = 0; b < BATCH; b++)
            acc[b] += __shfl_down_sync(0xffffffffu, acc[b], off);
    if (lane == 0) {
        float bv = bias ? bias[warp] : 0.f;
        #pragma unroll
        for (int b = 0; b < BATCH; b++) {
            float v = acc[b] + bv;
            if (relu) v = fmaxf(v, 0.f);
            out[(size_t)b*N + warp] = v;
        }
    }
}

// ----------------------------- chamfer (smem-staged B, float4 quads) ----------
__global__ void chamfer_min_kernel(const float* __restrict__ A, int na,
                                   const float* __restrict__ Bp, int nb_,
                                   float* __restrict__ part) {
    __shared__ float sb[2432*3];
    __shared__ float red[256];
    int chunks = gridDim.x / BATCH;
    int b = blockIdx.x / chunks, ch = blockIdx.x % chunks;
    int t = threadIdx.x;
    const float* bp = Bp + (size_t)b*nb_*3;
    for (int i = t; i < nb_*3; i += 256) sb[i] = bp[i];
    __syncthreads();
    int i = ch*256 + t;
    float s = 0.f;
    if (i < na) {
        const float* ap = A + ((size_t)b*na + i)*3;
        float ax = ap[0], ay = ap[1], az = ap[2];
        const float4* sv4 = (const float4*)sb;
        float mn = 3.0e38f;
        int nq = nb_ >> 2;
        for (int j = 0; j < nq; j++) {
            float4 q0 = sv4[j*3+0];
            float4 q1 = sv4[j*3+1];
            float4 q2 = sv4[j*3+2];
            float dx, dy, dz, d;
            dx = q0.x-ax; dy = q0.y-ay; dz = q0.z-az;
            d = dx*dx + dy*dy + dz*dz; mn = fminf(mn, d);
            dx = q0.w-ax; dy = q1.x-ay; dz = q1.y-az;
            d = dx*dx + dy*dy + dz*dz; mn = fminf(mn, d);
            dx = q1.z-ax; dy = q1.w-ay; dz = q2.x-az;
            d = dx*dx + dy*dy + dz*dz; mn = fminf(mn, d);
            dx = q2.y-ax; dy = q2.z-ay; dz = q2.w-az;
            d = dx*dx + dy*dy + dz*dz; mn = fminf(mn, d);
        }
        s = sqrtf(fmaxf(mn, 1e-12f));
    }
    red[t] = s;
    __syncthreads();
    for (int r = 128; r > 0; r >>= 1) {
        if (t < r) red[t] += red[t+r];
        __syncthreads();
    }
    if (t == 0) part[blockIdx.x] = red[0];
}
__global__ void chamfer_final_kernel(const float* __restrict__ p1, int n1,
                                     const float* __restrict__ p2, int n2,
                                     float w, int tot1, int tot2,
                                     float* __restrict__ slot) {
    double s1 = 0.0, s2 = 0.0;
    for (int i = 0; i < n1; i++) s1 += p1[i];
    for (int i = 0; i < n2; i++) s2 += p2[i];
    *slot = w * 0.5f * (float)(s1/tot1 + s2/tot2);
}

// ----------------------------- huber latent loss ------------------------------
__global__ void huber_kernel(const float* __restrict__ f1, const float* __restrict__ f2,
                             int n, float w, float* __restrict__ slot) {
    int t = threadIdx.x;
    float s = 0.f;
    for (int i = t; i < n; i += 256) {
        float d = f1[i] - f2[i];
        float ad = fabsf(d);
        s += (ad < 1.f) ? 0.5f*d*d : (ad - 0.5f);
    }
    __shared__ float red[256];
    red[t] = s;
    __syncthreads();
    for (int r = 128; r > 0; r >>= 1) {
        if (t < r) red[t] += red[t+r];
        __syncthreads();
    }
    if (t == 0) *slot = w * red[0] / n;
}

// ----------------------------- normals ----------------------------------------
__device__ void eig3_min(double a00, double a01, double a02,
                         double a11, double a12, double a22,
                         double* vx, double* vy, double* vz) {
    double p1 = a01*a01 + a02*a02 + a12*a12;
    double ex = 1, ey = 0, ez = 0;
    if (p1 < 1e-300) {
        if (a00 <= a11 && a00 <= a22) { ex=1; ey=0; ez=0; }
        else if (a11 <= a22)          { ex=0; ey=1; ez=0; }
        else                          { ex=0; ey=0; ez=1; }
    } else {
        double q  = (a00 + a11 + a22) / 3.0;
        double b00 = a00-q, b11 = a11-q, b22 = a22-q;
        double p2 = b00*b00 + b11*b11 + b22*b22 + 2.0*p1;
        double p  = sqrt(p2/6.0);
        double inv = 1.0/p;
        double c00 = b00*inv, c01 = a01*inv, c02 = a02*inv;
        double c11 = b11*inv, c12 = a12*inv, c22 = b22*inv;
        double detB = c00*(c11*c22 - c12*c12) - c01*(c01*c22 - c12*c02) + c02*(c01*c12 - c11*c02);
        double r = detB * 0.5;
        r = fmin(1.0, fmax(-1.0, r));
        double phi = acos(r) / 3.0;
        double l1 = q + 2.0*p*cos(phi);
        double l3 = q + 2.0*p*cos(phi + 2.0943951023931953);
        double l2 = 3.0*q - l1 - l3;
        double A1[3][3] = {{a00-l1, a01, a02}, {a01, a11-l1, a12}, {a02, a12, a22-l1}};
        double A2[3][3] = {{a00-l2, a01, a02}, {a01, a11-l2, a12}, {a02, a12, a22-l2}};
        double Mby[3][3];
        for (int i = 0; i < 3; i++)
            for (int j = 0; j < 3; j++)
                Mby[i][j] = A1[i][0]*A2[0][j] + A1[i][1]*A2[1][j] + A1[i][2]*A2[2][j];
        double bestn = -1.0;
        for (int j = 0; j < 3; j++) {
            double nx = Mby[0][j], ny = Mby[1][j], nz = Mby[2][j];
            double nn = nx*nx + ny*ny + nz*nz;
            if (nn > bestn) { bestn = nn; ex = nx; ey = ny; ez = nz; }
        }
        if (bestn < 1e-200) {
            double C[3][3] = {{a00-l3, a01, a02}, {a01, a11-l3, a12}, {a02, a12, a22-l3}};
            bestn = -1.0;
            int pairs[3][2] = {{0,1},{0,2},{1,2}};
            for (int pp = 0; pp < 3; pp++) {
                int r0 = pairs[pp][0], r1 = pairs[pp][1];
                double nx = C[r0][1]*C[r1][2] - C[r0][2]*C[r1][1];
                double ny = C[r0][2]*C[r1][0] - C[r0][0]*C[r1][2];
                double nz = C[r0][0]*C[r1][1] - C[r0][1]*C[r1][0];
                double nn = nx*nx + ny*ny + nz*nz;
                if (nn > bestn) { bestn = nn; ex = nx; ey = ny; ez = nz; }
            }
            if (bestn < 1e-200) { ex = 1; ey = 0; ez = 0; }
        }
    }
    double nrm = sqrt(ex*ex + ey*ey + ez*ez);
    double invn = 1.0 / nrm;
    *vx = ex*invn; *vy = ey*invn; *vz = ez*invn;
}

__global__ void normals_kernel(const float* __restrict__ pred,
                               const int* __restrict__ idx,
                               float* __restrict__ nrm) {
    int gid = blockIdx.x*256 + threadIdx.x;
    if (gid >= BATCH*NPTS) return;
    int b = gid / NPTS;
    const int* ip = idx + (size_t)gid*NBH;
    const float* base = pred + (size_t)b*NPTS*3;
    float px[NBH], py[NBH], pz[NBH];
    float sx = 0.f, sy = 0.f, sz = 0.f;
    #pragma unroll 4
    for (int k = 0; k < NBH; k++) {
        const float* p = base + (size_t)ip[k]*3;
        px[k] = p[0]; py[k] = p[1]; pz[k] = p[2];
        sx += px[k]; sy += py[k]; sz += pz[k];
    }
    float mx = sx*(1.f/NBH), my = sy*(1.f/NBH), mz = sz*(1.f/NBH);
    float cxx=0.f, cxy=0.f, cxz=0.f, cyy=0.f, cyz=0.f, czz=0.f;
    #pragma unroll 4
    for (int k = 0; k < NBH; k++) {
        float dx = px[k]-mx, dy = py[k]-my, dz = pz[k]-mz;
        cxx += dx*dx; cxy += dx*dy; cxz += dx*dz;
        cyy += dy*dy; cyz += dy*dz; czz += dz*dz;
    }
    float inv = 1.f/NBH;
    double vx, vy, vz;
    eig3_min((double)(cxx*inv), (double)(cxy*inv), (double)(cxz*inv),
             (double)(cyy*inv), (double)(cyz*inv), (double)(czz*inv),
             &vx, &vy, &vz);
    const float* xp = pred + (size_t)gid*3;
    double proj = 0.0;
    #pragma unroll 4
    for (int k = 0; k < NBH; k++)
        proj += (px[k]-xp[0])*vx + (py[k]-xp[1])*vy + (pz[k]-xp[2])*vz;
    double sgn = (proj >= 0.0) ? 1.0 : -1.0;
    nrm[(size_t)gid*3+0] = (float)(vx*sgn);
    nrm[(size_t)gid*3+1] = (float)(vy*sgn);
    nrm[(size_t)gid*3+2] = (float)(vz*sgn);
}

__global__ void manifold_kernel(const float* __restrict__ nrm,
                                const int* __restrict__ idx,
                                float* __restrict__ outstd) {
    int gid = blockIdx.x*256 + threadIdx.x;
    if (gid >= BATCH*NPTS) return;
    int b = gid / NPTS;
    const int* ip = idx + (size_t)gid*NBH;
    const float* base = nrm + (size_t)b*NPTS*3;
    const float* a = base + (size_t)ip[0]*3;
    float ax = a[0], ay = a[1], az = a[2];
    float an = fmaxf(sqrtf(ax*ax + ay*ay + az*az), 1e-6f);
    float vals[SUP];
    #pragma unroll
    for (int j = 0; j < SUP; j++) {
        const float* nj = base + (size_t)ip[j]*3;
        float nn = fmaxf(sqrtf(nj[0]*nj[0] + nj[1]*nj[1] + nj[2]*nj[2]), 1e-6f);
        float cosv = (ax*nj[0] + ay*nj[1] + az*nj[2]) / (an * nn);
        vals[j] = 1.f - cosv;
    }
    float mean = 0.f;
    #pragma unroll
    for (int j = 0; j < SUP; j++) mean += vals[j];
    mean /= SUP;
    float var = 0.f;
    #pragma unroll
    for (int j = 0; j < SUP; j++) { float d = vals[j]-mean; var += d*d; }
    var /= (SUP - 1);
    outstd[gid] = sqrtf(fmaxf(var, 0.f));
}

__global__ void mean_kernel(const float* __restrict__ in, int n, float w,
                            float* __restrict__ slot) {
    int t = threadIdx.x;
    float s = 0.f;
    for (int i = t; i < n; i += 256) s += in[i];
    __shared__ float red[256];
    red[t] = s;
    __syncthreads();
    for (int r = 128; r > 0; r >>= 1) {
        if (t < r) red[t] += red[t+r];
        __syncthreads();
    }
    if (t == 0) *slot = w * red[0] / n;
}

__global__ void final_kernel(const float* __restrict__ loss, float* __restrict__ out) {
    out[0] = loss[0] + loss[1] + loss[2] + loss[3];
    out[1] = loss[0];
    out[2] = loss[1];
    out[3] = loss[2];
    out[4] = loss[3];
}

// ----------------------------- host-side orchestration -----------------------
static void* sym(const void* symbol) {
    void* p = nullptr;
    cudaGetSymbolAddress(&p, symbol);
    return p;
}

struct Params {
    const float *W1,*b1,*g1,*be1,*m1,*v1,*W2,*b2,*W3,*b3,*g2,*be2,*m2,*v2,*W4,*b4;
    const float *D1W,*D1b,*D2W,*D2b,*D3W,*D3b,*D4W,*D4b;
};

#define GEMM_SMEM (3*GSTG*4)

static void run_encoder(const float* x, int npts, float* feat_out, const Params& P,
                        float* gmax, float* gb, float* cmpart, cudaStream_t st) {
    int M = BATCH * npts;
    int nchunks = npts / 256;
    uint32_t* h1h = (uint32_t*)sym(g_h1h); uint32_t* h1l = (uint32_t*)sym(g_h1l);
    uint32_t* h2h = (uint32_t*)sym(g_h2h); uint32_t* h2l = (uint32_t*)sym(g_h2l);
    uint32_t* h4h = (uint32_t*)sym(g_h4h); uint32_t* h4l = (uint32_t*)sym(g_h4l);
    uint32_t* w2h = (uint32_t*)sym(g_w2h); uint32_t* w2l = (uint32_t*)sym(g_w2l);
    uint32_t* w3h = (uint32_t*)sym(g_w3h); uint32_t* w3l = (uint32_t*)sym(g_w3l);
    uint32_t* w4h = (uint32_t*)sym(g_w4h); uint32_t* w4l = (uint32_t*)sym(g_w4l);

    layer1_kernel<<<(M*64 + 255)/256, 256, 0, st>>>(x, P.W1, P.b1, P.g1, P.be1, P.m1, P.v1,
                                                    h1h, h1l, M);
    {
        dim3 grid(256/128, M/256);
        gemm_tc<<<grid, 512, GEMM_SMEM, st>>>(h1h, h1l, 64, w2h, w2l, 64, M, 256, 128,
                               P.b2, nullptr, 1, nullptr, nullptr, nullptr, nullptr, 0,
                               h2h, h2l, cmpart);
    }
    colmax_final<<<(BATCH*256 + 255)/256, 256, 0, st>>>(cmpart, nchunks, 256, gmax);
    gemv16_kernel<<<(512 + 7)/8, 256, 0, st>>>(gmax, 256, P.W3, 512, 512, 256, P.b3, 0, gb);
    {
        dim3 grid(512/128, M/256);
        gemm_tc<<<grid, 512, GEMM_SMEM, st>>>(h2h, h2l, 128, w3h, w3l, 128, M, 512, 256,
                               nullptr, gb, npts, P.g2, P.be2, P.m2, P.v2, 1,
                               h4h, h4l, nullptr);
    }
    {
        dim3 grid(1024/128, M/256);
        gemm_tc<<<grid, 512, GEMM_SMEM, st>>>(h4h, h4l, 256, w4h, w4l, 256, M, 1024, 512,
                               P.b4, nullptr, 1, nullptr, nullptr, nullptr, nullptr, 0,
                               nullptr, nullptr, cmpart);
    }
    colmax_final<<<(BATCH*1024 + 255)/256, 256, 0, st>>>(cmpart, nchunks, 1024, feat_out);
}

extern "C" void kernel_launch(void* const* d_in, const int* in_sizes, int n_in,
                              void* d_out, int out_size) {
    const float* pts = (const float*)d_in[0];
    Params P;
    P.W1  = (const float*)d_in[1];  P.b1  = (const float*)d_in[2];
    P.g1  = (const float*)d_in[3];  P.be1 = (const float*)d_in[4];
    P.m1  = (const float*)d_in[5];  P.v1  = (const float*)d_in[6];
    P.W2  = (const float*)d_in[7];  P.b2  = (const float*)d_in[8];
    P.W3  = (const float*)d_in[9];  P.b3  = (const float*)d_in[10];
    P.g2  = (const float*)d_in[11]; P.be2 = (const float*)d_in[12];
    P.m2  = (const float*)d_in[13]; P.v2  = (const float*)d_in[14];
    P.W4  = (const float*)d_in[15]; P.b4  = (const float*)d_in[16];
    P.D1W = (const float*)d_in[17]; P.D1b = (const float*)d_in[18];
    P.D2W = (const float*)d_in[19]; P.D2b = (const float*)d_in[20];
    P.D3W = (const float*)d_in[21]; P.D3b = (const float*)d_in[22];
    P.D4W = (const float*)d_in[23]; P.D4b = (const float*)d_in[24];
    float* out = (float*)d_out;

    static cudaStream_t s1 = nullptr, s2 = nullptr, s3 = nullptr;
    static cudaEvent_t evStart = nullptr, evSplit = nullptr, evPred = nullptr;
    static cudaEvent_t evA = nullptr, evB = nullptr, evD = nullptr;
    if (!s1) {
        cudaStreamCreateWithFlags(&s1, cudaStreamNonBlocking);
        cudaStreamCreateWithFlags(&s2, cudaStreamNonBlocking);
        cudaStreamCreateWithFlags(&s3, cudaStreamNonBlocking);
        cudaEventCreateWithFlags(&evStart, cudaEventDisableTiming);
        cudaEventCreateWithFlags(&evSplit, cudaEventDisableTiming);
        cudaEventCreateWithFlags(&evPred,  cudaEventDisableTiming);
        cudaEventCreateWithFlags(&evA, cudaEventDisableTiming);
        cudaEventCreateWithFlags(&evB, cudaEventDisableTiming);
        cudaEventCreateWithFlags(&evD, cudaEventDisableTiming);
        cudaFuncSetAttribute(gemm_tc, cudaFuncAttributeMaxDynamicSharedMemorySize, GEMM_SMEM);
    }

    int*   fps    = (int*)  sym(g_fps);
    float* center = (float*)sym(g_center);
    int*   knnc   = (int*)  sym(g_knnc);
    float* reb0   = (float*)sym(g_reb0);
    float* reb1   = (float*)sym(g_reb1);
    float* encin2 = (float*)sym(g_encin2);
    float* gmax   = (float*)sym(g_gmax);
    float* gb     = (float*)sym(g_gb);
    float* cmpart = (float*)sym(g_cmpart);
    float* feat   = (float*)sym(g_feat);
    float* feat2  = (float*)sym(g_feat2);
    float* dec1   = (float*)sym(g_dec1);
    float* dec2   = (float*)sym(g_dec2);
    float* dec3   = (float*)sym(g_dec3);
    float* pred   = (float*)sym(g_pred);
    int*   knngA  = (int*)  sym(g_knngA);
    int*   knngB  = (int*)  sym(g_knngB);
    int*   knngC  = (int*)  sym(g_knngC);
    float* gathA  = (float*)sym(g_gathA);
    float* gathB  = (float*)sym(g_gathB);
    int*   knnp   = (int*)  sym(g_knnp);
    float* nrm    = (float*)sym(g_normals);
    float* stdbuf = (float*)sym(g_std);
    float* partA1 = (float*)sym(g_partA1);
    float* partA2 = (float*)sym(g_partA2);
    float* partB1 = (float*)sym(g_partB1);
    float* partB2 = (float*)sym(g_partB2);
    float* loss   = (float*)sym(g_loss);

    // fork: weight splitting on s1, concurrent with FPS/grouping on main
    cudaEventRecord(evStart, 0);
    cudaStreamWaitEvent(s1, evStart, 0);
    splitw_kernel<<<(256*64 + 255)/256, 256, 0, s1>>>(P.W2, 128, 0, 256*64, 64,
                                               (uint32_t*)sym(g_w2h), (uint32_t*)sym(g_w2l));
    splitw_kernel<<<(512*128 + 255)/256, 256, 0, s1>>>(P.W3, 512, 256, 512*128, 128,
                                               (uint32_t*)sym(g_w3h), (uint32_t*)sym(g_w3l));
    splitw_kernel<<<(1024*256 + 255)/256, 256, 0, s1>>>(P.W4, 512, 0, 1024*256, 256,
                                               (uint32_t*)sym(g_w4h), (uint32_t*)sym(g_w4l));
    cudaEventRecord(evSplit, s1);

    // 1. FPS + center + grouping (main)
    fps_kernel<<<BATCH, 512>>>(pts, fps);
    gather3_kernel<<<(BATCH*NG + 255)/256, 256>>>(pts, NPTS, fps, NG, NG, center);
    knn_kernel<<<BATCH*NG, 256>>>(center, NG, NG, pts, NPTS, GS, knnc);
    gather3_kernel<<<(BATCH*2048 + 255)/256, 256>>>(pts, NPTS, knnc, NG*GS, 2048, reb0);
    gather3_kernel<<<(BATCH*1024 + 255)/256, 256>>>(pts, NPTS, knnc + O1*GS, NG*GS, 1024, reb1);

    // join splits before encoder GEMMs
    cudaStreamWaitEvent(0, evSplit, 0);

    // 2. encoder pass A + decoder (main)
    run_encoder(reb0, 2048, feat, P, gmax, gb, cmpart, 0);
    gemv16_kernel<<<2048/8, 256>>>(feat, 1024, P.D1W, 1024, 2048, 1024, P.D1b, 1, dec1);
    gemv16_kernel<<<2048/8, 256>>>(dec1, 2048, P.D2W, 2048, 2048, 2048, P.D2b, 1, dec2);
    gemv16_kernel<<<2048/8, 256>>>(dec2, 2048, P.D3W, 2048, 2048, 2048, P.D3b, 1, dec3);
    gemv16_kernel<<<6144/8, 256>>>(dec3, 2048, P.D4W, 2048, 6144, 2048, P.D4b, 0, pred);

    // fork after pred
    cudaEventRecord(evPred, 0);
    cudaStreamWaitEvent(s1, evPred, 0);
    cudaStreamWaitEvent(s2, evPred, 0);
    cudaStreamWaitEvent(s3, evPred, 0);

    // branch A (s1): l_recon
    knn_kernel<<<BATCH*64, 256, 0, s1>>>(center, NG, 64, pred, NPTS, NBRK, knngA);
    gather3_kernel<<<(BATCH*2432 + 255)/256, 256, 0, s1>>>(pred, NPTS, knngA, 64*NBRK, 2432, gathA);
    chamfer_min_kernel<<<BATCH*8, 256, 0, s1>>>(reb0, 2048, gathA, 2432, partA1);
    chamfer_min_kernel<<<BATCH*10, 256, 0, s1>>>(gathA, 2432, reb0, 2048, partA2);
    chamfer_final_kernel<<<1, 1, 0, s1>>>(partA1, BATCH*8, partA2, BATCH*10, 1.0f,
                                          BATCH*2048, BATCH*2432, loss + 0);
    cudaEventRecord(evA, s1);

    // branch B (s2): l_match
    knn_kernel<<<BATCH*32, 256, 0, s2>>>(center + O1*3, NG, 32, pred, NPTS, NBRK, knngB);
    gather3_kernel<<<(BATCH*1216 + 255)/256, 256, 0, s2>>>(pred, NPTS, knngB, 32*NBRK, 1216, gathB);
    chamfer_min_kernel<<<BATCH*4, 256, 0, s2>>>(reb1, 1024, gathB, 1216, partB1);
    chamfer_min_kernel<<<BATCH*5, 256, 0, s2>>>(gathB, 1216, reb1, 1024, partB2);
    chamfer_final_kernel<<<1, 1, 0, s2>>>(partB1, BATCH*4, partB2, BATCH*5, 1.0f,
                                          BATCH*1024, BATCH*1216, loss + 1);
    cudaEventRecord(evB, s2);

    // branch D (s3): l_man (heaviest independent chain)
    knn_kernel<<<BATCH*NPTS, 256, 0, s3>>>(pred, NPTS, NPTS, pred, NPTS, NBH, knnp);
    normals_kernel<<<(BATCH*NPTS + 255)/256, 256, 0, s3>>>(pred, knnp, nrm);
    manifold_kernel<<<(BATCH*NPTS + 255)/256, 256, 0, s3>>>(nrm, knnp, stdbuf);
    mean_kernel<<<1, 256, 0, s3>>>(stdbuf, BATCH*NPTS, 0.1f, loss + 3);
    cudaEventRecord(evD, s3);

    // branch C (main): l_latent encoder pass
    knn_kernel<<<BATCH*32, 256>>>(center + O2*3, NG, 32, pred, NPTS, GS, knngC);
    gather3_kernel<<<(BATCH*1024 + 255)/256, 256>>>(pred, NPTS, knngC, 32*GS, 1024, encin2);
    run_encoder(encin2, 1024, feat2, P, gmax, gb, cmpart, 0);
    huber_kernel<<<1, 256>>>(feat, feat2, BATCH*FEATD, 1.0f, loss + 2);

    // join all branches, then final
    cudaStreamWaitEvent(0, evA, 0);
    cudaStreamWaitEvent(0, evB, 0);
    cudaStreamWaitEvent(0, evD, 0);
    final_kernel<<<1, 1>>>(loss, out);
}